// round 14
// baseline (speedup 1.0000x reference)
#include <cuda_runtime.h>
#include <cuda_fp16.h>

#define D_MODEL 1024
#define HEADS   16
#define DEPTH   64
#define BATCH   4
#define SEQ     2048
#define MROWS   (BATCH * SEQ)   /* 8192 */
#define BH      (BATCH * HEADS) /* 64   */

// ---- static scratch (allocation-free per harness rules) ----
__device__ __half Xh[(size_t)MROWS * D_MODEL];        // x in fp16
__device__ __half Wth[(size_t)4 * D_MODEL * D_MODEL]; // W^T fp16: [4][n][k]
__device__ __half Qh[(size_t)BH * SEQ * DEPTH];       // [bh][s][d], pre-scaled
__device__ __half Kh[(size_t)BH * SEQ * DEPTH];       // [bh][s][d]
__device__ __half Vh[(size_t)BH * DEPTH * SEQ];       // TRANSPOSED [bh][d][s]
__device__ __half Oh[(size_t)BH * SEQ * DEPTH];       // [bh][s][d]

__device__ __half* QKVout16[3];

#define SCL_F (0.125f * 1.4426950408889634f)   /* 1/sqrt(64) * log2(e) */

// ---------------- helpers ----------------
__device__ __forceinline__ unsigned su(const void* p) {
    return (unsigned)__cvta_generic_to_shared(p);
}
__device__ __forceinline__ void cp16(unsigned d, const void* s) {
    asm volatile("cp.async.cg.shared.global [%0], [%1], 16;" :: "r"(d), "l"(s));
}
__device__ __forceinline__ void cpcommit() { asm volatile("cp.async.commit_group;"); }
__device__ __forceinline__ void cpwait0() { asm volatile("cp.async.wait_group 0;"); }
__device__ __forceinline__ void cpwait1() { asm volatile("cp.async.wait_group 1;"); }

// pack two floats -> half2 (x = low element, y = high element)
__device__ __forceinline__ unsigned h2pack(float x, float y) {
    unsigned r;
    asm("cvt.rn.f16x2.f32 %0, %1, %2;" : "=r"(r) : "f"(y), "f"(x));
    return r;
}
__device__ __forceinline__ unsigned h2u(__half2 h) { return *(unsigned*)&h; }
__device__ __forceinline__ __half2 u2h(unsigned u) { return *(__half2*)&u; }

// fp16 mma m16n8k16, fp32 accumulate
__device__ __forceinline__ void mma16(float* c, const unsigned* a, const unsigned* b) {
    asm volatile(
        "mma.sync.aligned.m16n8k16.row.col.f32.f16.f16.f32 "
        "{%0,%1,%2,%3},{%4,%5,%6,%7},{%8,%9},{%0,%1,%2,%3};"
        : "+f"(c[0]), "+f"(c[1]), "+f"(c[2]), "+f"(c[3])
        : "r"(a[0]), "r"(a[1]), "r"(a[2]), "r"(a[3]), "r"(b[0]), "r"(b[1]));
}
// fp16 mma m16n8k16, fp16 accumulate (C/D packed half2 x2)
__device__ __forceinline__ void mma16h(unsigned* c, const unsigned* a, const unsigned* b) {
    asm volatile(
        "mma.sync.aligned.m16n8k16.row.col.f16.f16.f16.f16 "
        "{%0,%1},{%2,%3,%4,%5},{%6,%7},{%0,%1};"
        : "+r"(c[0]), "+r"(c[1])
        : "r"(a[0]), "r"(a[1]), "r"(a[2]), "r"(a[3]), "r"(b[0]), "r"(b[1]));
}

#define ST 72   /* smem row stride in halves = 144 bytes */

// ---------------- prep: x -> fp16 ----------------
__global__ __launch_bounds__(256) void cvt_x_kernel(
    const float* __restrict__ in, __half* __restrict__ out, int n4)
{
    int i = blockIdx.x * 256 + threadIdx.x;
    if (i < n4) {
        float4 v = ((const float4*)in)[i];
        uint2 o;
        o.x = h2pack(v.x, v.y);
        o.y = h2pack(v.z, v.w);
        ((uint2*)out)[i] = o;
    }
}

// ---------------- prep: transpose weights -> fp16  Wth[z][n][k] ----------------
__global__ __launch_bounds__(256) void cvt_wT_kernel(
    const float* __restrict__ w0, const float* __restrict__ w1,
    const float* __restrict__ w2, const float* __restrict__ w3,
    __half* __restrict__ out)
{
    __shared__ float t[32][33];
    const float* src = (blockIdx.z == 0) ? w0 : (blockIdx.z == 1) ? w1
                       : (blockIdx.z == 2) ? w2 : w3;
    __half* dst = out + (size_t)blockIdx.z * (size_t)D_MODEL * D_MODEL;
    int bx = blockIdx.x * 32;   // k tile
    int by = blockIdx.y * 32;   // n tile
#pragma unroll
    for (int j = 0; j < 4; j++)
        t[threadIdx.y + j * 8][threadIdx.x] =
            src[(size_t)(bx + threadIdx.y + j * 8) * D_MODEL + by + threadIdx.x];
    __syncthreads();
#pragma unroll
    for (int j = 0; j < 4; j++)
        dst[(size_t)(by + threadIdx.y + j * 8) * D_MODEL + bx + threadIdx.x] =
            __float2half_rn(t[threadIdx.x][threadIdx.y + j * 8]);
}

// ============================================================
// Kernel 1: MERGED QKV proj, fp16 m16n8k16 f32-acc (unchanged)
// ============================================================
#define GEMM_SMEM (4 * 128 * ST * 2)   /* 73728 bytes */

__global__ __launch_bounds__(256, 2) void proj_qkv_kernel(
    const __half* __restrict__ A, const __half* __restrict__ Wbase,
    const float* __restrict__ bq, const float* __restrict__ bk,
    const float* __restrict__ bv)
{
    extern __shared__ __half smh[];
    __half* Ah[2] = { smh, smh + 128 * ST };
    __half* Bh[2] = { smh + 2 * 128 * ST, smh + 3 * 128 * ST };

    const int z = blockIdx.z;
    const __half* W = Wbase + (size_t)z * D_MODEL * D_MODEL;
    const float* bias = (z == 0) ? bq : (z == 1) ? bk : bv;
    __half* out = QKVout16[z];

    const int tid = threadIdx.x;
    const int m0 = blockIdx.y * 128, n0 = blockIdx.x * 128;
    const int warp = tid >> 5, lane = tid & 31;
    const int g = lane >> 2, t = lane & 3;
    const int wm = (warp & 3) * 32, wn = (warp >> 2) * 64;

    float acc[2][8][4] = {};

#define PROJ_LOAD(buf, k0)                                                        \
    do {                                                                          \
        _Pragma("unroll")                                                         \
        for (int i = 0; i < 4; i++) {                                             \
            int id = tid + i * 256; int r = id >> 3, cc = id & 7;                 \
            cp16(su(&Ah[buf][r * ST + cc * 8]),                                   \
                 A + (size_t)(m0 + r) * 1024 + (k0) + cc * 8);                    \
        }                                                                         \
        _Pragma("unroll")                                                         \
        for (int i = 0; i < 4; i++) {                                             \
            int id = tid + i * 256; int r = id >> 3, cc = id & 7;                 \
            cp16(su(&Bh[buf][r * ST + cc * 8]),                                   \
                 W + (size_t)(n0 + r) * 1024 + (k0) + cc * 8);                    \
        }                                                                         \
        cpcommit();                                                               \
    } while (0)

    PROJ_LOAD(0, 0);
    for (int it = 0; it < 16; it++) {
        if (it + 1 < 16) { PROJ_LOAD((it + 1) & 1, (it + 1) * 64); cpwait1(); }
        else cpwait0();
        __syncthreads();
        const __half* a_s = Ah[it & 1];
        const __half* b_s = Bh[it & 1];
#pragma unroll
        for (int ks = 0; ks < 4; ks++) {
            unsigned a[2][4], b[8][2];
#pragma unroll
            for (int ma = 0; ma < 2; ma++) {
                int rb = wm + ma * 16;
                a[ma][0] = *(const unsigned*)&a_s[(rb + g) * ST + ks * 16 + 2 * t];
                a[ma][1] = *(const unsigned*)&a_s[(rb + g + 8) * ST + ks * 16 + 2 * t];
                a[ma][2] = *(const unsigned*)&a_s[(rb + g) * ST + ks * 16 + 2 * t + 8];
                a[ma][3] = *(const unsigned*)&a_s[(rb + g + 8) * ST + ks * 16 + 2 * t + 8];
            }
#pragma unroll
            for (int nb = 0; nb < 8; nb++) {
                int nr = wn + nb * 8 + g;
                b[nb][0] = *(const unsigned*)&b_s[nr * ST + ks * 16 + 2 * t];
                b[nb][1] = *(const unsigned*)&b_s[nr * ST + ks * 16 + 2 * t + 8];
            }
#pragma unroll
            for (int nb = 0; nb < 8; nb++)
#pragma unroll
                for (int ma = 0; ma < 2; ma++)
                    mma16(acc[ma][nb], a[ma], b[nb]);
        }
        __syncthreads();
    }

    const float scale = (z == 0) ? SCL_F : 1.0f;
#pragma unroll
    for (int ma = 0; ma < 2; ma++)
#pragma unroll
        for (int nb = 0; nb < 8; nb++) {
            int c0 = n0 + wn + nb * 8 + 2 * t;
            float b0 = __ldg(&bias[c0]), b1 = __ldg(&bias[c0 + 1]);
            int h = c0 >> 6, d = c0 & 63;
#pragma unroll
            for (int rr = 0; rr < 2; rr++) {
                int r = m0 + wm + ma * 16 + g + rr * 8;
                int bb = r >> 11, ss = r & 2047;
                float vx = (acc[ma][nb][rr * 2 + 0] + b0) * scale;
                float vy = (acc[ma][nb][rr * 2 + 1] + b1) * scale;
                if (z != 2) {
                    *(unsigned*)&out[(((size_t)(bb * 16 + h)) * 2048 + ss) * 64 + d] =
                        h2pack(vx, vy);
                } else {
                    __half* vb = out + (size_t)(bb * 16 + h) * 64 * 2048;
                    vb[(size_t)d * 2048 + ss]       = __float2half_rn(vx);
                    vb[(size_t)(d + 1) * 2048 + ss] = __float2half_rn(vy);
                }
            }
        }
}

// ============================================================
// Kernel 2: FLASH ATTENTION — 256-row Q tile, 8 warps x 32 rows,
//   2 CTAs/SM -> 16 warps/SM. Per-warp loop identical to R13.
// ============================================================
#define FLASH_SMEM ((256 * ST + 4 * 64 * ST) * 2)   /* 73728 bytes */
#define ONES2 0x3C003C00u                            /* half2(1,1) */

__global__ __launch_bounds__(256, 2) void flash_attn_kernel()
{
    extern __shared__ __half smh[];
    __half* Qs = smh;                                    // 256 x ST
    __half* Ks[2] = { smh + 256 * ST, smh + 256 * ST + 64 * ST };
    __half* Vs[2] = { smh + 256 * ST + 2 * 64 * ST, smh + 256 * ST + 3 * 64 * ST };

    const int bh = blockIdx.y;
    const int m0 = blockIdx.x * 256;
    const __half* Qp = Qh + (size_t)bh * SEQ * DEPTH;
    const __half* Kp = Kh + (size_t)bh * SEQ * DEPTH;
    const __half* Vp = Vh + (size_t)bh * DEPTH * SEQ;   // [d][s]
    __half* Op = Oh + (size_t)bh * SEQ * DEPTH;

    const int tid = threadIdx.x;
    const int warp = tid >> 5, lane = tid & 31;
    const int g = lane >> 2, t = lane & 3;
    const int wq0 = warp * 32;                  // warp owns 32 of the 256 Q rows
    const unsigned FULL = 0xffffffffu;

    // Q tile 256x64 halves: 8 cp16 per thread (2048 cp16 total)
#pragma unroll
    for (int i = 0; i < 8; i++) {
        int id = tid + i * 256; int r = id >> 3, c = id & 7;
        cp16(su(&Qs[r * ST + c * 8]), Qp + (size_t)(m0 + r) * 64 + c * 8);
    }
    cpcommit();

    // KV tiles 64x64: 2 cp16 per thread each
#define KV_LOAD(buf, kv0)                                                         \
    do {                                                                          \
        _Pragma("unroll")                                                         \
        for (int i = 0; i < 2; i++) {                                             \
            int id = tid + i * 256; int r = id >> 3, c = id & 7;                  \
            cp16(su(&Ks[buf][r * ST + c * 8]),                                    \
                 Kp + (size_t)((kv0) + r) * 64 + c * 8);                          \
        }                                                                         \
        _Pragma("unroll")                                                         \
        for (int i = 0; i < 2; i++) {                                             \
            int id = tid + i * 256; int r = id >> 3, c = id & 7;                  \
            cp16(su(&Vs[buf][r * ST + c * 8]),                                    \
                 Vp + (size_t)r * 2048 + (kv0) + c * 8);                          \
        }                                                                         \
        cpcommit();                                                               \
    } while (0)

    KV_LOAD(0, 0);
    cpwait1();
    __syncthreads();

    // running max per ma: half2(lo = row g, hi = row g+8)
    __half2 mr2[2];
    mr2[0] = __float2half2_rn(-60000.f);
    mr2[1] = __float2half2_rn(-60000.f);

    // o[ma][0..7] = output cols; o[ma][8] = row-sum column (l), fp32 acc
    float o[2][9][4] = {};

    for (int j = 0; j < 32; j++) {
        if (j + 1 < 32) { KV_LOAD((j + 1) & 1, (j + 1) * 64); cpwait1(); }
        else cpwait0();
        __syncthreads();
        const __half* ks = Ks[j & 1];
        const __half* vs = Vs[j & 1];

        // ---- S = Q K^T : fp16 accumulate; C-frag IS the half2 layout ----
        unsigned acc2[2][8][2];
#pragma unroll
        for (int ma = 0; ma < 2; ma++)
#pragma unroll
            for (int nb = 0; nb < 8; nb++) {
                acc2[ma][nb][0] = 0u; acc2[ma][nb][1] = 0u;
            }

#pragma unroll
        for (int kb = 0; kb < 4; kb++) {
            unsigned a[2][4];
#pragma unroll
            for (int ma = 0; ma < 2; ma++) {
                int rb = wq0 + ma * 16;
                a[ma][0] = *(const unsigned*)&Qs[(rb + g) * ST + kb * 16 + 2 * t];
                a[ma][1] = *(const unsigned*)&Qs[(rb + g + 8) * ST + kb * 16 + 2 * t];
                a[ma][2] = *(const unsigned*)&Qs[(rb + g) * ST + kb * 16 + 2 * t + 8];
                a[ma][3] = *(const unsigned*)&Qs[(rb + g + 8) * ST + kb * 16 + 2 * t + 8];
            }
#pragma unroll
            for (int nb = 0; nb < 8; nb++) {
                unsigned b[2];
                int nr = nb * 8 + g;
                b[0] = *(const unsigned*)&ks[nr * ST + kb * 16 + 2 * t];
                b[1] = *(const unsigned*)&ks[nr * ST + kb * 16 + 2 * t + 8];
                mma16h(acc2[0][nb], a[0], b);
                mma16h(acc2[1][nb], a[1], b);
            }
        }

        // ---- max reduction in half2 domain ----
        float al[4];
#pragma unroll
        for (int ma = 0; ma < 2; ma++) {
            __half2 x0 = u2h(acc2[ma][0][0]), x1 = u2h(acc2[ma][0][1]);
#pragma unroll
            for (int nb = 1; nb < 8; nb++) {
                x0 = __hmax2(x0, u2h(acc2[ma][nb][0]));
                x1 = __hmax2(x1, u2h(acc2[ma][nb][1]));
            }
            __half2 mm = __halves2half2(
                __hmax(__low2half(x0), __high2half(x0)),
                __hmax(__low2half(x1), __high2half(x1)));
            mm = __hmax2(mm, u2h(__shfl_xor_sync(FULL, h2u(mm), 1)));
            mm = __hmax2(mm, u2h(__shfl_xor_sync(FULL, h2u(mm), 2)));
            __half2 nm = __hmax2(mr2[ma], mm);
            __half2 a2 = h2exp2(__hsub2(mr2[ma], nm));
            mr2[ma] = nm;
            al[ma * 2 + 0] = __low2float(a2);
            al[ma * 2 + 1] = __high2float(a2);
        }

        // ---- rescale O (incl. the l column) ----
#pragma unroll
        for (int ma = 0; ma < 2; ma++)
#pragma unroll
            for (int nb = 0; nb < 9; nb++) {
                o[ma][nb][0] *= al[ma * 2 + 0]; o[ma][nb][1] *= al[ma * 2 + 0];
                o[ma][nb][2] *= al[ma * 2 + 1]; o[ma][nb][3] *= al[ma * 2 + 1];
            }

        // ---- O += P @ V, P = exp2(acc2 - m) on the fly; nb==8 = ones col ----
#pragma unroll
        for (int kb = 0; kb < 4; kb++) {
            unsigned ap[2][4];
#pragma unroll
            for (int ma = 0; ma < 2; ma++) {
                __half2 m0b = __low2half2(mr2[ma]);
                __half2 m1b = __high2half2(mr2[ma]);
                ap[ma][0] = h2u(h2exp2(__hsub2(u2h(acc2[ma][2 * kb][0]),     m0b)));
                ap[ma][1] = h2u(h2exp2(__hsub2(u2h(acc2[ma][2 * kb][1]),     m1b)));
                ap[ma][2] = h2u(h2exp2(__hsub2(u2h(acc2[ma][2 * kb + 1][0]), m0b)));
                ap[ma][3] = h2u(h2exp2(__hsub2(u2h(acc2[ma][2 * kb + 1][1]), m1b)));
            }
#pragma unroll
            for (int nb = 0; nb < 9; nb++) {
                unsigned b[2];
                if (nb < 8) {
                    int nr = nb * 8 + g;
                    b[0] = *(const unsigned*)&vs[nr * ST + kb * 16 + 2 * t];
                    b[1] = *(const unsigned*)&vs[nr * ST + kb * 16 + 2 * t + 8];
                } else {
                    b[0] = ONES2; b[1] = ONES2;
                }
                mma16(o[0][nb], ap[0], b);
                mma16(o[1][nb], ap[1], b);
            }
        }
        __syncthreads();
    }

    // ---- epilogue: O /= l (from ones column), fp16 store ----
#pragma unroll
    for (int ma = 0; ma < 2; ma++) {
        float inv0 = 1.f / o[ma][8][0];
        float inv1 = 1.f / o[ma][8][2];
#pragma unroll
        for (int nb = 0; nb < 8; nb++) {
            int c0 = nb * 8 + 2 * t;
            {
                int r = m0 + wq0 + ma * 16 + g;
                *(unsigned*)&Op[(size_t)r * 64 + c0] =
                    h2pack(o[ma][nb][0] * inv0, o[ma][nb][1] * inv0);
            }
            {
                int r = m0 + wq0 + ma * 16 + g + 8;
                *(unsigned*)&Op[(size_t)r * 64 + c0] =
                    h2pack(o[ma][nb][2] * inv1, o[ma][nb][3] * inv1);
            }
        }
    }
}

// ============================================================
// Kernel 3: out = untranspose(Oh) @ wo + bo, fp16 mma, fp32 out
// ============================================================
__global__ __launch_bounds__(256, 2) void outproj_kernel(
    const __half* __restrict__ W, const float* __restrict__ bo,
    float* __restrict__ out)
{
    extern __shared__ __half smh[];
    __half* Ah[2] = { smh, smh + 128 * ST };
    __half* Bh[2] = { smh + 2 * 128 * ST, smh + 3 * 128 * ST };

    const int tid = threadIdx.x;
    const int m0 = blockIdx.y * 128, n0 = blockIdx.x * 128;
    const int warp = tid >> 5, lane = tid & 31;
    const int g = lane >> 2, t = lane & 3;
    const int wm = (warp & 3) * 32, wn = (warp >> 2) * 64;

    float acc[2][8][4] = {};

#define OP_LOAD(buf, k0)                                                          \
    do {                                                                          \
        _Pragma("unroll")                                                         \
        for (int i = 0; i < 4; i++) {                                             \
            int id = tid + i * 256; int r = id >> 3, cc = id & 7;                 \
            int m = m0 + r; int k = (k0) + cc * 8;                                \
            const __half* src = Oh + (((size_t)((m >> 11) * 16 + (k >> 6))) * 2048 \
                                      + (m & 2047)) * 64 + (k & 63);              \
            cp16(su(&Ah[buf][r * ST + cc * 8]), src);                             \
        }                                                                         \
        _Pragma("unroll")                                                         \
        for (int i = 0; i < 4; i++) {                                             \
            int id = tid + i * 256; int r = id >> 3, cc = id & 7;                 \
            cp16(su(&Bh[buf][r * ST + cc * 8]),                                   \
                 W + (size_t)(n0 + r) * 1024 + (k0) + cc * 8);                    \
        }                                                                         \
        cpcommit();                                                               \
    } while (0)

    OP_LOAD(0, 0);
    for (int it = 0; it < 16; it++) {
        if (it + 1 < 16) { OP_LOAD((it + 1) & 1, (it + 1) * 64); cpwait1(); }
        else cpwait0();
        __syncthreads();
        const __half* a_s = Ah[it & 1];
        const __half* b_s = Bh[it & 1];
#pragma unroll
        for (int ks = 0; ks < 4; ks++) {
            unsigned a[2][4], b[8][2];
#pragma unroll
            for (int ma = 0; ma < 2; ma++) {
                int rb = wm + ma * 16;
                a[ma][0] = *(const unsigned*)&a_s[(rb + g) * ST + ks * 16 + 2 * t];
                a[ma][1] = *(const unsigned*)&a_s[(rb + g + 8) * ST + ks * 16 + 2 * t];
                a[ma][2] = *(const unsigned*)&a_s[(rb + g) * ST + ks * 16 + 2 * t + 8];
                a[ma][3] = *(const unsigned*)&a_s[(rb + g + 8) * ST + ks * 16 + 2 * t + 8];
            }
#pragma unroll
            for (int nb = 0; nb < 8; nb++) {
                int nr = wn + nb * 8 + g;
                b[nb][0] = *(const unsigned*)&b_s[nr * ST + ks * 16 + 2 * t];
                b[nb][1] = *(const unsigned*)&b_s[nr * ST + ks * 16 + 2 * t + 8];
            }
#pragma unroll
            for (int nb = 0; nb < 8; nb++)
#pragma unroll
                for (int ma = 0; ma < 2; ma++)
                    mma16(acc[ma][nb], a[ma], b[nb]);
        }
        __syncthreads();
    }

#pragma unroll
    for (int ma = 0; ma < 2; ma++)
#pragma unroll
        for (int nb = 0; nb < 8; nb++) {
            int c0 = n0 + wn + nb * 8 + 2 * t;
            float b0 = __ldg(&bo[c0]), b1 = __ldg(&bo[c0 + 1]);
#pragma unroll
            for (int rr = 0; rr < 2; rr++) {
                int r = m0 + wm + ma * 16 + g + rr * 8;
                float2 v;
                v.x = acc[ma][nb][rr * 2 + 0] + b0;
                v.y = acc[ma][nb][rr * 2 + 1] + b1;
                *(float2*)&out[(size_t)r * 1024 + c0] = v;
            }
        }
}

// ============================================================
extern "C" void kernel_launch(void* const* d_in, const int* in_sizes, int n_in,
                              void* d_out, int out_size)
{
    const float* x  = (const float*)d_in[0];
    const float* wq = (const float*)d_in[1];
    const float* bq = (const float*)d_in[2];
    const float* wk = (const float*)d_in[3];
    const float* bk = (const float*)d_in[4];
    const float* wv = (const float*)d_in[5];
    const float* bv = (const float*)d_in[6];
    const float* wo = (const float*)d_in[7];
    const float* bo = (const float*)d_in[8];
    float* out = (float*)d_out;

    cudaFuncSetAttribute(proj_qkv_kernel,   cudaFuncAttributeMaxDynamicSharedMemorySize, GEMM_SMEM);
    cudaFuncSetAttribute(flash_attn_kernel, cudaFuncAttributeMaxDynamicSharedMemorySize, FLASH_SMEM);
    cudaFuncSetAttribute(outproj_kernel,    cudaFuncAttributeMaxDynamicSharedMemorySize, GEMM_SMEM);

    __half* Xh_p;  cudaGetSymbolAddress((void**)&Xh_p, Xh);
    __half* Wt_p;  cudaGetSymbolAddress((void**)&Wt_p, Wth);
    __half* Qp;    cudaGetSymbolAddress((void**)&Qp, Qh);
    __half* Kp;    cudaGetSymbolAddress((void**)&Kp, Kh);
    __half* Vp;    cudaGetSymbolAddress((void**)&Vp, Vh);

    static __half* h_tab[3];
    h_tab[0] = Qp; h_tab[1] = Kp; h_tab[2] = Vp;
    void* tab_dev; cudaGetSymbolAddress(&tab_dev, QKVout16);
    cudaMemcpyAsync(tab_dev, h_tab, sizeof(h_tab), cudaMemcpyHostToDevice);

    dim3 blk(256);
    const size_t WSZ = (size_t)D_MODEL * D_MODEL;

    {
        int n4 = (MROWS * D_MODEL) / 4;
        cvt_x_kernel<<<(n4 + 255) / 256, blk>>>(x, Xh_p, n4);
        cvt_wT_kernel<<<dim3(32, 32, 4), dim3(32, 8)>>>(wq, wk, wv, wo, Wt_p);
    }

    dim3 gqkv(D_MODEL / 128, MROWS / 128, 3);
    proj_qkv_kernel<<<gqkv, blk, GEMM_SMEM>>>(Xh_p, Wt_p, bq, bk, bv);

    flash_attn_kernel<<<dim3(SEQ / 256, BH), blk, FLASH_SMEM>>>();

    outproj_kernel<<<dim3(D_MODEL / 128, MROWS / 128), blk, GEMM_SMEM>>>(
        Wt_p + 3 * WSZ, bo, out);
}

// round 15
// speedup vs baseline: 1.2681x; 1.2681x over previous
#include <cuda_runtime.h>
#include <cuda_fp16.h>

#define D_MODEL 1024
#define HEADS   16
#define DEPTH   64
#define BATCH   4
#define SEQ     2048
#define MROWS   (BATCH * SEQ)   /* 8192 */
#define BH      (BATCH * HEADS) /* 64   */

// ---- static scratch (allocation-free per harness rules) ----
__device__ __half Xh[(size_t)MROWS * D_MODEL];        // x in fp16
__device__ __half Wth[(size_t)4 * D_MODEL * D_MODEL]; // W^T fp16: [4][n][k]
__device__ __half Qh[(size_t)BH * SEQ * DEPTH];       // [bh][s][d], pre-scaled
__device__ __half Kh[(size_t)BH * SEQ * DEPTH];       // [bh][s][d]
__device__ __half Vh[(size_t)BH * DEPTH * SEQ];       // TRANSPOSED [bh][d][s]
__device__ __half Oh[(size_t)BH * SEQ * DEPTH];       // [bh][s][d]

__device__ __half* QKVout16[3];

#define SCL_F (0.125f * 1.4426950408889634f)   /* 1/sqrt(64) * log2(e) */

// ---------------- helpers ----------------
__device__ __forceinline__ unsigned su(const void* p) {
    return (unsigned)__cvta_generic_to_shared(p);
}
__device__ __forceinline__ void cp16(unsigned d, const void* s) {
    asm volatile("cp.async.cg.shared.global [%0], [%1], 16;" :: "r"(d), "l"(s));
}
__device__ __forceinline__ void cpcommit() { asm volatile("cp.async.commit_group;"); }
__device__ __forceinline__ void cpwait0() { asm volatile("cp.async.wait_group 0;"); }
__device__ __forceinline__ void cpwait1() { asm volatile("cp.async.wait_group 1;"); }

// pack two floats -> half2 (x = low element, y = high element)
__device__ __forceinline__ unsigned h2pack(float x, float y) {
    unsigned r;
    asm("cvt.rn.f16x2.f32 %0, %1, %2;" : "=r"(r) : "f"(y), "f"(x));
    return r;
}
__device__ __forceinline__ unsigned h2u(__half2 h) { return *(unsigned*)&h; }
__device__ __forceinline__ __half2 u2h(unsigned u) { return *(__half2*)&u; }

// fp16 mma m16n8k16, fp32 accumulate
__device__ __forceinline__ void mma16(float* c, const unsigned* a, const unsigned* b) {
    asm volatile(
        "mma.sync.aligned.m16n8k16.row.col.f32.f16.f16.f32 "
        "{%0,%1,%2,%3},{%4,%5,%6,%7},{%8,%9},{%0,%1,%2,%3};"
        : "+f"(c[0]), "+f"(c[1]), "+f"(c[2]), "+f"(c[3])
        : "r"(a[0]), "r"(a[1]), "r"(a[2]), "r"(a[3]), "r"(b[0]), "r"(b[1]));
}
// fp16 mma m16n8k16, fp16 accumulate (C/D packed half2 x2)
__device__ __forceinline__ void mma16h(unsigned* c, const unsigned* a, const unsigned* b) {
    asm volatile(
        "mma.sync.aligned.m16n8k16.row.col.f16.f16.f16.f16 "
        "{%0,%1},{%2,%3,%4,%5},{%6,%7},{%0,%1};"
        : "+r"(c[0]), "+r"(c[1])
        : "r"(a[0]), "r"(a[1]), "r"(a[2]), "r"(a[3]), "r"(b[0]), "r"(b[1]));
}
// ldmatrix x4 (non-transposed): lane 4r+c of each 8-lane group addresses row r
__device__ __forceinline__ void ldsm4(unsigned* r, unsigned addr) {
    asm volatile("ldmatrix.sync.aligned.m8n8.x4.shared.b16 {%0,%1,%2,%3}, [%4];"
        : "=r"(r[0]), "=r"(r[1]), "=r"(r[2]), "=r"(r[3]) : "r"(addr));
}

#define ST 72   /* smem row stride in halves = 144 bytes */

// ---------------- prep: x -> fp16 ----------------
__global__ __launch_bounds__(256) void cvt_x_kernel(
    const float* __restrict__ in, __half* __restrict__ out, int n4)
{
    int i = blockIdx.x * 256 + threadIdx.x;
    if (i < n4) {
        float4 v = ((const float4*)in)[i];
        uint2 o;
        o.x = h2pack(v.x, v.y);
        o.y = h2pack(v.z, v.w);
        ((uint2*)out)[i] = o;
    }
}

// ---------------- prep: transpose weights -> fp16  Wth[z][n][k] ----------------
__global__ __launch_bounds__(256) void cvt_wT_kernel(
    const float* __restrict__ w0, const float* __restrict__ w1,
    const float* __restrict__ w2, const float* __restrict__ w3,
    __half* __restrict__ out)
{
    __shared__ float t[32][33];
    const float* src = (blockIdx.z == 0) ? w0 : (blockIdx.z == 1) ? w1
                       : (blockIdx.z == 2) ? w2 : w3;
    __half* dst = out + (size_t)blockIdx.z * (size_t)D_MODEL * D_MODEL;
    int bx = blockIdx.x * 32;   // k tile
    int by = blockIdx.y * 32;   // n tile
#pragma unroll
    for (int j = 0; j < 4; j++)
        t[threadIdx.y + j * 8][threadIdx.x] =
            src[(size_t)(bx + threadIdx.y + j * 8) * D_MODEL + by + threadIdx.x];
    __syncthreads();
#pragma unroll
    for (int j = 0; j < 4; j++)
        dst[(size_t)(by + threadIdx.y + j * 8) * D_MODEL + bx + threadIdx.x] =
            __float2half_rn(t[threadIdx.x][threadIdx.y + j * 8]);
}

// ============================================================
// Kernel 1: MERGED QKV proj, fp16 m16n8k16, ldmatrix loads
// ============================================================
#define GEMM_SMEM (4 * 128 * ST * 2)   /* 73728 bytes */

__global__ __launch_bounds__(256, 2) void proj_qkv_kernel(
    const __half* __restrict__ A, const __half* __restrict__ Wbase,
    const float* __restrict__ bq, const float* __restrict__ bk,
    const float* __restrict__ bv)
{
    extern __shared__ __half smh[];
    __half* Ah[2] = { smh, smh + 128 * ST };
    __half* Bh[2] = { smh + 2 * 128 * ST, smh + 3 * 128 * ST };

    const int z = blockIdx.z;
    const __half* W = Wbase + (size_t)z * D_MODEL * D_MODEL;
    const float* bias = (z == 0) ? bq : (z == 1) ? bk : bv;
    __half* out = QKVout16[z];

    const int tid = threadIdx.x;
    const int m0 = blockIdx.y * 128, n0 = blockIdx.x * 128;
    const int warp = tid >> 5, lane = tid & 31;
    const int g = lane >> 2, t = lane & 3;
    const int lm = lane >> 3, lr = lane & 7;   // ldmatrix: matrix id, row
    const int wm = (warp & 3) * 32, wn = (warp >> 2) * 64;

    float acc[2][8][4] = {};

#define PROJ_LOAD(buf, k0)                                                        \
    do {                                                                          \
        _Pragma("unroll")                                                         \
        for (int i = 0; i < 4; i++) {                                             \
            int id = tid + i * 256; int r = id >> 3, cc = id & 7;                 \
            cp16(su(&Ah[buf][r * ST + cc * 8]),                                   \
                 A + (size_t)(m0 + r) * 1024 + (k0) + cc * 8);                    \
        }                                                                         \
        _Pragma("unroll")                                                         \
        for (int i = 0; i < 4; i++) {                                             \
            int id = tid + i * 256; int r = id >> 3, cc = id & 7;                 \
            cp16(su(&Bh[buf][r * ST + cc * 8]),                                   \
                 W + (size_t)(n0 + r) * 1024 + (k0) + cc * 8);                    \
        }                                                                         \
        cpcommit();                                                               \
    } while (0)

    PROJ_LOAD(0, 0);
    for (int it = 0; it < 16; it++) {
        if (it + 1 < 16) { PROJ_LOAD((it + 1) & 1, (it + 1) * 64); cpwait1(); }
        else cpwait0();
        __syncthreads();
        const __half* a_s = Ah[it & 1];
        const __half* b_s = Bh[it & 1];
#pragma unroll
        for (int ks = 0; ks < 4; ks++) {
            unsigned a[2][4], b[8][2];
            // A: 2 x ldmatrix.x4 — matrices: (rows,k0),(rows+8,k0),(rows,k8),(rows+8,k8)
#pragma unroll
            for (int ma = 0; ma < 2; ma++)
                ldsm4(a[ma], su(&a_s[(wm + ma * 16 + (lm & 1) * 8 + lr) * ST
                                     + ks * 16 + (lm >> 1) * 8]));
            // B: 4 x ldmatrix.x4 — matrices: (nb,k0),(nb,k8),(nb+1,k0),(nb+1,k8)
#pragma unroll
            for (int gb = 0; gb < 4; gb++) {
                unsigned r[4];
                ldsm4(r, su(&b_s[(wn + (gb * 2 + (lm >> 1)) * 8 + lr) * ST
                                 + ks * 16 + (lm & 1) * 8]));
                b[gb * 2][0] = r[0]; b[gb * 2][1] = r[1];
                b[gb * 2 + 1][0] = r[2]; b[gb * 2 + 1][1] = r[3];
            }
#pragma unroll
            for (int nb = 0; nb < 8; nb++)
#pragma unroll
                for (int ma = 0; ma < 2; ma++)
                    mma16(acc[ma][nb], a[ma], b[nb]);
        }
        __syncthreads();
    }

    const float scale = (z == 0) ? SCL_F : 1.0f;
#pragma unroll
    for (int ma = 0; ma < 2; ma++)
#pragma unroll
        for (int nb = 0; nb < 8; nb++) {
            int c0 = n0 + wn + nb * 8 + 2 * t;
            float b0 = __ldg(&bias[c0]), b1 = __ldg(&bias[c0 + 1]);
            int h = c0 >> 6, d = c0 & 63;
#pragma unroll
            for (int rr = 0; rr < 2; rr++) {
                int r = m0 + wm + ma * 16 + g + rr * 8;
                int bb = r >> 11, ss = r & 2047;
                float vx = (acc[ma][nb][rr * 2 + 0] + b0) * scale;
                float vy = (acc[ma][nb][rr * 2 + 1] + b1) * scale;
                if (z != 2) {
                    *(unsigned*)&out[(((size_t)(bb * 16 + h)) * 2048 + ss) * 64 + d] =
                        h2pack(vx, vy);
                } else {
                    __half* vb = out + (size_t)(bb * 16 + h) * 64 * 2048;
                    vb[(size_t)d * 2048 + ss]       = __float2half_rn(vx);
                    vb[(size_t)(d + 1) * 2048 + ss] = __float2half_rn(vy);
                }
            }
        }
}

// ============================================================
// Kernel 2: FLASH ATTENTION — R13 structure + ldmatrix loads
// ============================================================
#define FLASH_SMEM ((128 * ST + 4 * 64 * ST) * 2)   /* 55296 bytes */
#define ONES2 0x3C003C00u                            /* half2(1,1) */

__global__ __launch_bounds__(128, 2) void flash_attn_kernel()
{
    extern __shared__ __half smh[];
    __half* Qs = smh;                                    // 128 x ST
    __half* Ks[2] = { smh + 128 * ST, smh + 128 * ST + 64 * ST };
    __half* Vs[2] = { smh + 128 * ST + 2 * 64 * ST, smh + 128 * ST + 3 * 64 * ST };

    const int bh = blockIdx.y;
    const int m0 = blockIdx.x * 128;
    const __half* Qp = Qh + (size_t)bh * SEQ * DEPTH;
    const __half* Kp = Kh + (size_t)bh * SEQ * DEPTH;
    const __half* Vp = Vh + (size_t)bh * DEPTH * SEQ;   // [d][s]
    __half* Op = Oh + (size_t)bh * SEQ * DEPTH;

    const int tid = threadIdx.x;
    const int warp = tid >> 5, lane = tid & 31;
    const int g = lane >> 2, t = lane & 3;
    const int lm = lane >> 3, lr = lane & 7;
    const int wq0 = warp * 32;
    const unsigned FULL = 0xffffffffu;

#pragma unroll
    for (int i = 0; i < 8; i++) {
        int id = tid + i * 128; int r = id >> 3, c = id & 7;
        cp16(su(&Qs[r * ST + c * 8]), Qp + (size_t)(m0 + r) * 64 + c * 8);
    }
    cpcommit();

#define KV_LOAD(buf, kv0)                                                         \
    do {                                                                          \
        _Pragma("unroll")                                                         \
        for (int i = 0; i < 4; i++) {                                             \
            int id = tid + i * 128; int r = id >> 3, c = id & 7;                  \
            cp16(su(&Ks[buf][r * ST + c * 8]),                                    \
                 Kp + (size_t)((kv0) + r) * 64 + c * 8);                          \
        }                                                                         \
        _Pragma("unroll")                                                         \
        for (int i = 0; i < 4; i++) {                                             \
            int id = tid + i * 128; int r = id >> 3, c = id & 7;                  \
            cp16(su(&Vs[buf][r * ST + c * 8]),                                    \
                 Vp + (size_t)r * 2048 + (kv0) + c * 8);                          \
        }                                                                         \
        cpcommit();                                                               \
    } while (0)

    KV_LOAD(0, 0);
    cpwait1();
    __syncthreads();

    // running max per ma: half2(lo = row g, hi = row g+8)
    __half2 mr2[2];
    mr2[0] = __float2half2_rn(-60000.f);
    mr2[1] = __float2half2_rn(-60000.f);

    // o[ma][0..7] = output cols; o[ma][8] = row-sum column (l), fp32 acc
    float o[2][9][4] = {};

    for (int j = 0; j < 32; j++) {
        if (j + 1 < 32) { KV_LOAD((j + 1) & 1, (j + 1) * 64); cpwait1(); }
        else cpwait0();
        __syncthreads();
        const __half* ks = Ks[j & 1];
        const __half* vs = Vs[j & 1];

        // ---- S = Q K^T : fp16 accumulate; ldmatrix fragment loads ----
        unsigned acc2[2][8][2];
#pragma unroll
        for (int ma = 0; ma < 2; ma++)
#pragma unroll
            for (int nb = 0; nb < 8; nb++) {
                acc2[ma][nb][0] = 0u; acc2[ma][nb][1] = 0u;
            }

#pragma unroll
        for (int kb = 0; kb < 4; kb++) {
            unsigned a[2][4], b[8][2];
#pragma unroll
            for (int ma = 0; ma < 2; ma++)
                ldsm4(a[ma], su(&Qs[(wq0 + ma * 16 + (lm & 1) * 8 + lr) * ST
                                    + kb * 16 + (lm >> 1) * 8]));
#pragma unroll
            for (int gb = 0; gb < 4; gb++) {
                unsigned r[4];
                ldsm4(r, su(&ks[((gb * 2 + (lm >> 1)) * 8 + lr) * ST
                                + kb * 16 + (lm & 1) * 8]));
                b[gb * 2][0] = r[0]; b[gb * 2][1] = r[1];
                b[gb * 2 + 1][0] = r[2]; b[gb * 2 + 1][1] = r[3];
            }
#pragma unroll
            for (int nb = 0; nb < 8; nb++) {
                mma16h(acc2[0][nb], a[0], b[nb]);
                mma16h(acc2[1][nb], a[1], b[nb]);
            }
        }

        // ---- max reduction in half2 domain ----
        float al[4];
#pragma unroll
        for (int ma = 0; ma < 2; ma++) {
            __half2 x0 = u2h(acc2[ma][0][0]), x1 = u2h(acc2[ma][0][1]);
#pragma unroll
            for (int nb = 1; nb < 8; nb++) {
                x0 = __hmax2(x0, u2h(acc2[ma][nb][0]));
                x1 = __hmax2(x1, u2h(acc2[ma][nb][1]));
            }
            __half2 mm = __halves2half2(
                __hmax(__low2half(x0), __high2half(x0)),
                __hmax(__low2half(x1), __high2half(x1)));
            mm = __hmax2(mm, u2h(__shfl_xor_sync(FULL, h2u(mm), 1)));
            mm = __hmax2(mm, u2h(__shfl_xor_sync(FULL, h2u(mm), 2)));
            __half2 nm = __hmax2(mr2[ma], mm);
            __half2 a2 = h2exp2(__hsub2(mr2[ma], nm));
            mr2[ma] = nm;
            al[ma * 2 + 0] = __low2float(a2);
            al[ma * 2 + 1] = __high2float(a2);
        }

        // ---- rescale O (incl. the l column) ----
#pragma unroll
        for (int ma = 0; ma < 2; ma++)
#pragma unroll
            for (int nb = 0; nb < 9; nb++) {
                o[ma][nb][0] *= al[ma * 2 + 0]; o[ma][nb][1] *= al[ma * 2 + 0];
                o[ma][nb][2] *= al[ma * 2 + 1]; o[ma][nb][3] *= al[ma * 2 + 1];
            }

        // ---- O += P @ V, P = exp2(acc2 - m); V frags via ldmatrix ----
#pragma unroll
        for (int kb = 0; kb < 4; kb++) {
            unsigned ap[2][4], bv[8][2];
#pragma unroll
            for (int ma = 0; ma < 2; ma++) {
                __half2 m0b = __low2half2(mr2[ma]);
                __half2 m1b = __high2half2(mr2[ma]);
                ap[ma][0] = h2u(h2exp2(__hsub2(u2h(acc2[ma][2 * kb][0]),     m0b)));
                ap[ma][1] = h2u(h2exp2(__hsub2(u2h(acc2[ma][2 * kb][1]),     m1b)));
                ap[ma][2] = h2u(h2exp2(__hsub2(u2h(acc2[ma][2 * kb + 1][0]), m0b)));
                ap[ma][3] = h2u(h2exp2(__hsub2(u2h(acc2[ma][2 * kb + 1][1]), m1b)));
            }
#pragma unroll
            for (int gb = 0; gb < 4; gb++) {
                unsigned r[4];
                ldsm4(r, su(&vs[((gb * 2 + (lm >> 1)) * 8 + lr) * ST
                                + kb * 16 + (lm & 1) * 8]));
                bv[gb * 2][0] = r[0]; bv[gb * 2][1] = r[1];
                bv[gb * 2 + 1][0] = r[2]; bv[gb * 2 + 1][1] = r[3];
            }
#pragma unroll
            for (int nb = 0; nb < 9; nb++) {
                unsigned b[2];
                if (nb < 8) { b[0] = bv[nb][0]; b[1] = bv[nb][1]; }
                else        { b[0] = ONES2;     b[1] = ONES2;     }
                mma16(o[0][nb], ap[0], b);
                mma16(o[1][nb], ap[1], b);
            }
        }
        __syncthreads();
    }

    // ---- epilogue: O /= l (from ones column), fp16 store ----
#pragma unroll
    for (int ma = 0; ma < 2; ma++) {
        float inv0 = 1.f / o[ma][8][0];
        float inv1 = 1.f / o[ma][8][2];
#pragma unroll
        for (int nb = 0; nb < 8; nb++) {
            int c0 = nb * 8 + 2 * t;
            {
                int r = m0 + wq0 + ma * 16 + g;
                *(unsigned*)&Op[(size_t)r * 64 + c0] =
                    h2pack(o[ma][nb][0] * inv0, o[ma][nb][1] * inv0);
            }
            {
                int r = m0 + wq0 + ma * 16 + g + 8;
                *(unsigned*)&Op[(size_t)r * 64 + c0] =
                    h2pack(o[ma][nb][2] * inv1, o[ma][nb][3] * inv1);
            }
        }
    }
}

// ============================================================
// Kernel 3: out = untranspose(Oh) @ wo + bo, ldmatrix loads
// ============================================================
__global__ __launch_bounds__(256, 2) void outproj_kernel(
    const __half* __restrict__ W, const float* __restrict__ bo,
    float* __restrict__ out)
{
    extern __shared__ __half smh[];
    __half* Ah[2] = { smh, smh + 128 * ST };
    __half* Bh[2] = { smh + 2 * 128 * ST, smh + 3 * 128 * ST };

    const int tid = threadIdx.x;
    const int m0 = blockIdx.y * 128, n0 = blockIdx.x * 128;
    const int warp = tid >> 5, lane = tid & 31;
    const int g = lane >> 2, t = lane & 3;
    const int lm = lane >> 3, lr = lane & 7;
    const int wm = (warp & 3) * 32, wn = (warp >> 2) * 64;

    float acc[2][8][4] = {};

#define OP_LOAD(buf, k0)                                                          \
    do {                                                                          \
        _Pragma("unroll")                                                         \
        for (int i = 0; i < 4; i++) {                                             \
            int id = tid + i * 256; int r = id >> 3, cc = id & 7;                 \
            int m = m0 + r; int k = (k0) + cc * 8;                                \
            const __half* src = Oh + (((size_t)((m >> 11) * 16 + (k >> 6))) * 2048 \
                                      + (m & 2047)) * 64 + (k & 63);              \
            cp16(su(&Ah[buf][r * ST + cc * 8]), src);                             \
        }                                                                         \
        _Pragma("unroll")                                                         \
        for (int i = 0; i < 4; i++) {                                             \
            int id = tid + i * 256; int r = id >> 3, cc = id & 7;                 \
            cp16(su(&Bh[buf][r * ST + cc * 8]),                                   \
                 W + (size_t)(n0 + r) * 1024 + (k0) + cc * 8);                    \
        }                                                                         \
        cpcommit();                                                               \
    } while (0)

    OP_LOAD(0, 0);
    for (int it = 0; it < 16; it++) {
        if (it + 1 < 16) { OP_LOAD((it + 1) & 1, (it + 1) * 64); cpwait1(); }
        else cpwait0();
        __syncthreads();
        const __half* a_s = Ah[it & 1];
        const __half* b_s = Bh[it & 1];
#pragma unroll
        for (int ks = 0; ks < 4; ks++) {
            unsigned a[2][4], b[8][2];
#pragma unroll
            for (int ma = 0; ma < 2; ma++)
                ldsm4(a[ma], su(&a_s[(wm + ma * 16 + (lm & 1) * 8 + lr) * ST
                                     + ks * 16 + (lm >> 1) * 8]));
#pragma unroll
            for (int gb = 0; gb < 4; gb++) {
                unsigned r[4];
                ldsm4(r, su(&b_s[(wn + (gb * 2 + (lm >> 1)) * 8 + lr) * ST
                                 + ks * 16 + (lm & 1) * 8]));
                b[gb * 2][0] = r[0]; b[gb * 2][1] = r[1];
                b[gb * 2 + 1][0] = r[2]; b[gb * 2 + 1][1] = r[3];
            }
#pragma unroll
            for (int nb = 0; nb < 8; nb++)
#pragma unroll
                for (int ma = 0; ma < 2; ma++)
                    mma16(acc[ma][nb], a[ma], b[nb]);
        }
        __syncthreads();
    }

#pragma unroll
    for (int ma = 0; ma < 2; ma++)
#pragma unroll
        for (int nb = 0; nb < 8; nb++) {
            int c0 = n0 + wn + nb * 8 + 2 * t;
            float b0 = __ldg(&bo[c0]), b1 = __ldg(&bo[c0 + 1]);
#pragma unroll
            for (int rr = 0; rr < 2; rr++) {
                int r = m0 + wm + ma * 16 + g + rr * 8;
                float2 v;
                v.x = acc[ma][nb][rr * 2 + 0] + b0;
                v.y = acc[ma][nb][rr * 2 + 1] + b1;
                *(float2*)&out[(size_t)r * 1024 + c0] = v;
            }
        }
}

// ============================================================
extern "C" void kernel_launch(void* const* d_in, const int* in_sizes, int n_in,
                              void* d_out, int out_size)
{
    const float* x  = (const float*)d_in[0];
    const float* wq = (const float*)d_in[1];
    const float* bq = (const float*)d_in[2];
    const float* wk = (const float*)d_in[3];
    const float* bk = (const float*)d_in[4];
    const float* wv = (const float*)d_in[5];
    const float* bv = (const float*)d_in[6];
    const float* wo = (const float*)d_in[7];
    const float* bo = (const float*)d_in[8];
    float* out = (float*)d_out;

    cudaFuncSetAttribute(proj_qkv_kernel,   cudaFuncAttributeMaxDynamicSharedMemorySize, GEMM_SMEM);
    cudaFuncSetAttribute(flash_attn_kernel, cudaFuncAttributeMaxDynamicSharedMemorySize, FLASH_SMEM);
    cudaFuncSetAttribute(outproj_kernel,    cudaFuncAttributeMaxDynamicSharedMemorySize, GEMM_SMEM);

    __half* Xh_p;  cudaGetSymbolAddress((void**)&Xh_p, Xh);
    __half* Wt_p;  cudaGetSymbolAddress((void**)&Wt_p, Wth);
    __half* Qp;    cudaGetSymbolAddress((void**)&Qp, Qh);
    __half* Kp;    cudaGetSymbolAddress((void**)&Kp, Kh);
    __half* Vp;    cudaGetSymbolAddress((void**)&Vp, Vh);

    static __half* h_tab[3];
    h_tab[0] = Qp; h_tab[1] = Kp; h_tab[2] = Vp;
    void* tab_dev; cudaGetSymbolAddress(&tab_dev, QKVout16);
    cudaMemcpyAsync(tab_dev, h_tab, sizeof(h_tab), cudaMemcpyHostToDevice);

    dim3 blk(256);
    const size_t WSZ = (size_t)D_MODEL * D_MODEL;

    {
        int n4 = (MROWS * D_MODEL) / 4;
        cvt_x_kernel<<<(n4 + 255) / 256, blk>>>(x, Xh_p, n4);
        cvt_wT_kernel<<<dim3(32, 32, 4), dim3(32, 8)>>>(wq, wk, wv, wo, Wt_p);
    }

    dim3 gqkv(D_MODEL / 128, MROWS / 128, 3);
    proj_qkv_kernel<<<gqkv, blk, GEMM_SMEM>>>(Xh_p, Wt_p, bq, bk, bv);

    flash_attn_kernel<<<dim3(SEQ / 128, BH), dim3(128), FLASH_SMEM>>>();

    outproj_kernel<<<dim3(D_MODEL / 128, MROWS / 128), blk, GEMM_SMEM>>>(
        Wt_p + 3 * WSZ, bo, out);
}

// round 16
// speedup vs baseline: 1.3167x; 1.0383x over previous
#include <cuda_runtime.h>
#include <cuda_fp16.h>

#define D_MODEL 1024
#define HEADS   16
#define DEPTH   64
#define BATCH   4
#define SEQ     2048
#define MROWS   (BATCH * SEQ)   /* 8192 */
#define BH      (BATCH * HEADS) /* 64   */

// ---- static scratch (allocation-free per harness rules) ----
__device__ __half Xh[(size_t)MROWS * D_MODEL];        // x in fp16
__device__ __half Wth[(size_t)4 * D_MODEL * D_MODEL]; // W^T fp16: [4][n][k]
__device__ __half Qh[(size_t)BH * SEQ * DEPTH];       // [bh][s][d], pre-scaled
__device__ __half Kh[(size_t)BH * SEQ * DEPTH];       // [bh][s][d]
__device__ __half Vh[(size_t)BH * DEPTH * SEQ];       // TRANSPOSED [bh][d][s]
__device__ __half Oh[(size_t)BH * SEQ * DEPTH];       // [bh][s][d]

__device__ __half* QKVout16[3];

#define SCL_F (0.125f * 1.4426950408889634f)   /* 1/sqrt(64) * log2(e) */

// ---------------- helpers ----------------
__device__ __forceinline__ unsigned su(const void* p) {
    return (unsigned)__cvta_generic_to_shared(p);
}
__device__ __forceinline__ void cp16(unsigned d, const void* s) {
    asm volatile("cp.async.cg.shared.global [%0], [%1], 16;" :: "r"(d), "l"(s));
}
__device__ __forceinline__ void cpcommit() { asm volatile("cp.async.commit_group;"); }
__device__ __forceinline__ void cpwait0() { asm volatile("cp.async.wait_group 0;"); }
__device__ __forceinline__ void cpwait1() { asm volatile("cp.async.wait_group 1;"); }

// pack two floats -> half2 (x = low element, y = high element)
__device__ __forceinline__ unsigned h2pack(float x, float y) {
    unsigned r;
    asm("cvt.rn.f16x2.f32 %0, %1, %2;" : "=r"(r) : "f"(y), "f"(x));
    return r;
}
__device__ __forceinline__ unsigned h2u(__half2 h) { return *(unsigned*)&h; }
__device__ __forceinline__ __half2 u2h(unsigned u) { return *(__half2*)&u; }

// fp16 mma m16n8k16, fp32 accumulate
__device__ __forceinline__ void mma16(float* c, const unsigned* a, const unsigned* b) {
    asm volatile(
        "mma.sync.aligned.m16n8k16.row.col.f32.f16.f16.f32 "
        "{%0,%1,%2,%3},{%4,%5,%6,%7},{%8,%9},{%0,%1,%2,%3};"
        : "+f"(c[0]), "+f"(c[1]), "+f"(c[2]), "+f"(c[3])
        : "r"(a[0]), "r"(a[1]), "r"(a[2]), "r"(a[3]), "r"(b[0]), "r"(b[1]));
}
// fp16 mma m16n8k16, fp16 accumulate (C/D packed half2 x2)
__device__ __forceinline__ void mma16h(unsigned* c, const unsigned* a, const unsigned* b) {
    asm volatile(
        "mma.sync.aligned.m16n8k16.row.col.f16.f16.f16.f16 "
        "{%0,%1},{%2,%3,%4,%5},{%6,%7},{%0,%1};"
        : "+r"(c[0]), "+r"(c[1])
        : "r"(a[0]), "r"(a[1]), "r"(a[2]), "r"(a[3]), "r"(b[0]), "r"(b[1]));
}
// ldmatrix x4 (non-transposed): lane 4r+c of each 8-lane group addresses row r
__device__ __forceinline__ void ldsm4(unsigned* r, unsigned addr) {
    asm volatile("ldmatrix.sync.aligned.m8n8.x4.shared.b16 {%0,%1,%2,%3}, [%4];"
        : "=r"(r[0]), "=r"(r[1]), "=r"(r[2]), "=r"(r[3]) : "r"(addr));
}

#define ST 72   /* smem row stride in halves = 144 bytes */

// ---------------- prep: x -> fp16 ----------------
__global__ __launch_bounds__(256) void cvt_x_kernel(
    const float* __restrict__ in, __half* __restrict__ out, int n4)
{
    int i = blockIdx.x * 256 + threadIdx.x;
    if (i < n4) {
        float4 v = ((const float4*)in)[i];
        uint2 o;
        o.x = h2pack(v.x, v.y);
        o.y = h2pack(v.z, v.w);
        ((uint2*)out)[i] = o;
    }
}

// ---------------- prep: transpose weights -> fp16  Wth[z][n][k] ----------------
__global__ __launch_bounds__(256) void cvt_wT_kernel(
    const float* __restrict__ w0, const float* __restrict__ w1,
    const float* __restrict__ w2, const float* __restrict__ w3,
    __half* __restrict__ out)
{
    __shared__ float t[32][33];
    const float* src = (blockIdx.z == 0) ? w0 : (blockIdx.z == 1) ? w1
                       : (blockIdx.z == 2) ? w2 : w3;
    __half* dst = out + (size_t)blockIdx.z * (size_t)D_MODEL * D_MODEL;
    int bx = blockIdx.x * 32;   // k tile
    int by = blockIdx.y * 32;   // n tile
#pragma unroll
    for (int j = 0; j < 4; j++)
        t[threadIdx.y + j * 8][threadIdx.x] =
            src[(size_t)(bx + threadIdx.y + j * 8) * D_MODEL + by + threadIdx.x];
    __syncthreads();
#pragma unroll
    for (int j = 0; j < 4; j++)
        dst[(size_t)(by + threadIdx.y + j * 8) * D_MODEL + bx + threadIdx.x] =
            __float2half_rn(t[threadIdx.x][threadIdx.y + j * 8]);
}

// ============================================================
// Kernel 1: MERGED QKV proj, fp16 m16n8k16, ldmatrix loads
// ============================================================
#define GEMM_SMEM (4 * 128 * ST * 2)   /* 73728 bytes */

__global__ __launch_bounds__(256, 2) void proj_qkv_kernel(
    const __half* __restrict__ A, const __half* __restrict__ Wbase,
    const float* __restrict__ bq, const float* __restrict__ bk,
    const float* __restrict__ bv)
{
    extern __shared__ __half smh[];
    __half* Ah[2] = { smh, smh + 128 * ST };
    __half* Bh[2] = { smh + 2 * 128 * ST, smh + 3 * 128 * ST };

    const int z = blockIdx.z;
    const __half* W = Wbase + (size_t)z * D_MODEL * D_MODEL;
    const float* bias = (z == 0) ? bq : (z == 1) ? bk : bv;
    __half* out = QKVout16[z];

    const int tid = threadIdx.x;
    const int m0 = blockIdx.y * 128, n0 = blockIdx.x * 128;
    const int warp = tid >> 5, lane = tid & 31;
    const int g = lane >> 2, t = lane & 3;
    const int lm = lane >> 3, lr = lane & 7;   // ldmatrix: matrix id, row
    const int wm = (warp & 3) * 32, wn = (warp >> 2) * 64;

    float acc[2][8][4] = {};

#define PROJ_LOAD(buf, k0)                                                        \
    do {                                                                          \
        _Pragma("unroll")                                                         \
        for (int i = 0; i < 4; i++) {                                             \
            int id = tid + i * 256; int r = id >> 3, cc = id & 7;                 \
            cp16(su(&Ah[buf][r * ST + cc * 8]),                                   \
                 A + (size_t)(m0 + r) * 1024 + (k0) + cc * 8);                    \
        }                                                                         \
        _Pragma("unroll")                                                         \
        for (int i = 0; i < 4; i++) {                                             \
            int id = tid + i * 256; int r = id >> 3, cc = id & 7;                 \
            cp16(su(&Bh[buf][r * ST + cc * 8]),                                   \
                 W + (size_t)(n0 + r) * 1024 + (k0) + cc * 8);                    \
        }                                                                         \
        cpcommit();                                                               \
    } while (0)

    PROJ_LOAD(0, 0);
    for (int it = 0; it < 16; it++) {
        if (it + 1 < 16) { PROJ_LOAD((it + 1) & 1, (it + 1) * 64); cpwait1(); }
        else cpwait0();
        __syncthreads();
        const __half* a_s = Ah[it & 1];
        const __half* b_s = Bh[it & 1];
#pragma unroll
        for (int ks = 0; ks < 4; ks++) {
            unsigned a[2][4];
#pragma unroll
            for (int ma = 0; ma < 2; ma++)
                ldsm4(a[ma], su(&a_s[(wm + ma * 16 + (lm & 1) * 8 + lr) * ST
                                     + ks * 16 + (lm >> 1) * 8]));
#pragma unroll
            for (int gb = 0; gb < 4; gb++) {
                unsigned r[4];
                ldsm4(r, su(&b_s[(wn + (gb * 2 + (lm >> 1)) * 8 + lr) * ST
                                 + ks * 16 + (lm & 1) * 8]));
                mma16(acc[0][gb * 2],     a[0], &r[0]);
                mma16(acc[1][gb * 2],     a[1], &r[0]);
                mma16(acc[0][gb * 2 + 1], a[0], &r[2]);
                mma16(acc[1][gb * 2 + 1], a[1], &r[2]);
            }
        }
        __syncthreads();
    }

    const float scale = (z == 0) ? SCL_F : 1.0f;
#pragma unroll
    for (int ma = 0; ma < 2; ma++)
#pragma unroll
        for (int nb = 0; nb < 8; nb++) {
            int c0 = n0 + wn + nb * 8 + 2 * t;
            float b0 = __ldg(&bias[c0]), b1 = __ldg(&bias[c0 + 1]);
            int h = c0 >> 6, d = c0 & 63;
#pragma unroll
            for (int rr = 0; rr < 2; rr++) {
                int r = m0 + wm + ma * 16 + g + rr * 8;
                int bb = r >> 11, ss = r & 2047;
                float vx = (acc[ma][nb][rr * 2 + 0] + b0) * scale;
                float vy = (acc[ma][nb][rr * 2 + 1] + b1) * scale;
                if (z != 2) {
                    *(unsigned*)&out[(((size_t)(bb * 16 + h)) * 2048 + ss) * 64 + d] =
                        h2pack(vx, vy);
                } else {
                    __half* vb = out + (size_t)(bb * 16 + h) * 64 * 2048;
                    vb[(size_t)d * 2048 + ss]       = __float2half_rn(vx);
                    vb[(size_t)(d + 1) * 2048 + ss] = __float2half_rn(vy);
                }
            }
        }
}

// ============================================================
// Kernel 2: FLASH ATTENTION — R15 + fused ldsm/mma, 3 CTAs/SM
// ============================================================
#define FLASH_SMEM ((128 * ST + 4 * 64 * ST) * 2)   /* 55296 bytes */
#define ONES2 0x3C003C00u                            /* half2(1,1) */

__global__ __launch_bounds__(128, 3) void flash_attn_kernel()
{
    extern __shared__ __half smh[];
    __half* Qs = smh;                                    // 128 x ST
    __half* Ks[2] = { smh + 128 * ST, smh + 128 * ST + 64 * ST };
    __half* Vs[2] = { smh + 128 * ST + 2 * 64 * ST, smh + 128 * ST + 3 * 64 * ST };

    const int bh = blockIdx.y;
    const int m0 = blockIdx.x * 128;
    const __half* Qp = Qh + (size_t)bh * SEQ * DEPTH;
    const __half* Kp = Kh + (size_t)bh * SEQ * DEPTH;
    const __half* Vp = Vh + (size_t)bh * DEPTH * SEQ;   // [d][s]
    __half* Op = Oh + (size_t)bh * SEQ * DEPTH;

    const int tid = threadIdx.x;
    const int warp = tid >> 5, lane = tid & 31;
    const int g = lane >> 2, t = lane & 3;
    const int lm = lane >> 3, lr = lane & 7;
    const int wq0 = warp * 32;
    const unsigned FULL = 0xffffffffu;

#pragma unroll
    for (int i = 0; i < 8; i++) {
        int id = tid + i * 128; int r = id >> 3, c = id & 7;
        cp16(su(&Qs[r * ST + c * 8]), Qp + (size_t)(m0 + r) * 64 + c * 8);
    }
    cpcommit();

#define KV_LOAD(buf, kv0)                                                         \
    do {                                                                          \
        _Pragma("unroll")                                                         \
        for (int i = 0; i < 4; i++) {                                             \
            int id = tid + i * 128; int r = id >> 3, c = id & 7;                  \
            cp16(su(&Ks[buf][r * ST + c * 8]),                                    \
                 Kp + (size_t)((kv0) + r) * 64 + c * 8);                          \
        }                                                                         \
        _Pragma("unroll")                                                         \
        for (int i = 0; i < 4; i++) {                                             \
            int id = tid + i * 128; int r = id >> 3, c = id & 7;                  \
            cp16(su(&Vs[buf][r * ST + c * 8]),                                    \
                 Vp + (size_t)r * 2048 + (kv0) + c * 8);                          \
        }                                                                         \
        cpcommit();                                                               \
    } while (0)

    KV_LOAD(0, 0);
    cpwait1();
    __syncthreads();

    // running max per ma: half2(lo = row g, hi = row g+8)
    __half2 mr2[2];
    mr2[0] = __float2half2_rn(-60000.f);
    mr2[1] = __float2half2_rn(-60000.f);

    // o[ma][0..7] = output cols; o[ma][8] = row-sum column (l), fp32 acc
    float o[2][9][4] = {};

    for (int j = 0; j < 32; j++) {
        if (j + 1 < 32) { KV_LOAD((j + 1) & 1, (j + 1) * 64); cpwait1(); }
        else cpwait0();
        __syncthreads();
        const __half* ks = Ks[j & 1];
        const __half* vs = Vs[j & 1];

        // ---- S = Q K^T : fp16 accumulate; fused ldsm/mma ----
        unsigned acc2[2][8][2];
#pragma unroll
        for (int ma = 0; ma < 2; ma++)
#pragma unroll
            for (int nb = 0; nb < 8; nb++) {
                acc2[ma][nb][0] = 0u; acc2[ma][nb][1] = 0u;
            }

#pragma unroll
        for (int kb = 0; kb < 4; kb++) {
            unsigned a[2][4];
#pragma unroll
            for (int ma = 0; ma < 2; ma++)
                ldsm4(a[ma], su(&Qs[(wq0 + ma * 16 + (lm & 1) * 8 + lr) * ST
                                    + kb * 16 + (lm >> 1) * 8]));
#pragma unroll
            for (int gb = 0; gb < 4; gb++) {
                unsigned r[4];
                ldsm4(r, su(&ks[((gb * 2 + (lm >> 1)) * 8 + lr) * ST
                                + kb * 16 + (lm & 1) * 8]));
                mma16h(acc2[0][gb * 2],     a[0], &r[0]);
                mma16h(acc2[1][gb * 2],     a[1], &r[0]);
                mma16h(acc2[0][gb * 2 + 1], a[0], &r[2]);
                mma16h(acc2[1][gb * 2 + 1], a[1], &r[2]);
            }
        }

        // ---- max reduction in half2 domain ----
        float al[4];
#pragma unroll
        for (int ma = 0; ma < 2; ma++) {
            __half2 x0 = u2h(acc2[ma][0][0]), x1 = u2h(acc2[ma][0][1]);
#pragma unroll
            for (int nb = 1; nb < 8; nb++) {
                x0 = __hmax2(x0, u2h(acc2[ma][nb][0]));
                x1 = __hmax2(x1, u2h(acc2[ma][nb][1]));
            }
            __half2 mm = __halves2half2(
                __hmax(__low2half(x0), __high2half(x0)),
                __hmax(__low2half(x1), __high2half(x1)));
            mm = __hmax2(mm, u2h(__shfl_xor_sync(FULL, h2u(mm), 1)));
            mm = __hmax2(mm, u2h(__shfl_xor_sync(FULL, h2u(mm), 2)));
            __half2 nm = __hmax2(mr2[ma], mm);
            __half2 a2 = h2exp2(__hsub2(mr2[ma], nm));
            mr2[ma] = nm;
            al[ma * 2 + 0] = __low2float(a2);
            al[ma * 2 + 1] = __high2float(a2);
        }

        // ---- rescale O (incl. the l column) ----
#pragma unroll
        for (int ma = 0; ma < 2; ma++)
#pragma unroll
            for (int nb = 0; nb < 9; nb++) {
                o[ma][nb][0] *= al[ma * 2 + 0]; o[ma][nb][1] *= al[ma * 2 + 0];
                o[ma][nb][2] *= al[ma * 2 + 1]; o[ma][nb][3] *= al[ma * 2 + 1];
            }

        // ---- O += P @ V, P = exp2(acc2 - m); fused ldsm/mma ----
#pragma unroll
        for (int kb = 0; kb < 4; kb++) {
            unsigned ap[2][4];
#pragma unroll
            for (int ma = 0; ma < 2; ma++) {
                __half2 m0b = __low2half2(mr2[ma]);
                __half2 m1b = __high2half2(mr2[ma]);
                ap[ma][0] = h2u(h2exp2(__hsub2(u2h(acc2[ma][2 * kb][0]),     m0b)));
                ap[ma][1] = h2u(h2exp2(__hsub2(u2h(acc2[ma][2 * kb][1]),     m1b)));
                ap[ma][2] = h2u(h2exp2(__hsub2(u2h(acc2[ma][2 * kb + 1][0]), m0b)));
                ap[ma][3] = h2u(h2exp2(__hsub2(u2h(acc2[ma][2 * kb + 1][1]), m1b)));
            }
#pragma unroll
            for (int gb = 0; gb < 4; gb++) {
                unsigned r[4];
                ldsm4(r, su(&vs[((gb * 2 + (lm >> 1)) * 8 + lr) * ST
                                + kb * 16 + (lm & 1) * 8]));
                mma16(o[0][gb * 2],     ap[0], &r[0]);
                mma16(o[1][gb * 2],     ap[1], &r[0]);
                mma16(o[0][gb * 2 + 1], ap[0], &r[2]);
                mma16(o[1][gb * 2 + 1], ap[1], &r[2]);
            }
            // ones column (row-sum l)
            {
                unsigned onesb[2] = { ONES2, ONES2 };
                mma16(o[0][8], ap[0], onesb);
                mma16(o[1][8], ap[1], onesb);
            }
        }
        __syncthreads();
    }

    // ---- epilogue: O /= l (from ones column), fp16 store ----
#pragma unroll
    for (int ma = 0; ma < 2; ma++) {
        float inv0 = 1.f / o[ma][8][0];
        float inv1 = 1.f / o[ma][8][2];
#pragma unroll
        for (int nb = 0; nb < 8; nb++) {
            int c0 = nb * 8 + 2 * t;
            {
                int r = m0 + wq0 + ma * 16 + g;
                *(unsigned*)&Op[(size_t)r * 64 + c0] =
                    h2pack(o[ma][nb][0] * inv0, o[ma][nb][1] * inv0);
            }
            {
                int r = m0 + wq0 + ma * 16 + g + 8;
                *(unsigned*)&Op[(size_t)r * 64 + c0] =
                    h2pack(o[ma][nb][2] * inv1, o[ma][nb][3] * inv1);
            }
        }
    }
}

// ============================================================
// Kernel 3: out = untranspose(Oh) @ wo + bo, ldmatrix loads
// ============================================================
__global__ __launch_bounds__(256, 2) void outproj_kernel(
    const __half* __restrict__ W, const float* __restrict__ bo,
    float* __restrict__ out)
{
    extern __shared__ __half smh[];
    __half* Ah[2] = { smh, smh + 128 * ST };
    __half* Bh[2] = { smh + 2 * 128 * ST, smh + 3 * 128 * ST };

    const int tid = threadIdx.x;
    const int m0 = blockIdx.y * 128, n0 = blockIdx.x * 128;
    const int warp = tid >> 5, lane = tid & 31;
    const int g = lane >> 2, t = lane & 3;
    const int lm = lane >> 3, lr = lane & 7;
    const int wm = (warp & 3) * 32, wn = (warp >> 2) * 64;

    float acc[2][8][4] = {};

#define OP_LOAD(buf, k0)                                                          \
    do {                                                                          \
        _Pragma("unroll")                                                         \
        for (int i = 0; i < 4; i++) {                                             \
            int id = tid + i * 256; int r = id >> 3, cc = id & 7;                 \
            int m = m0 + r; int k = (k0) + cc * 8;                                \
            const __half* src = Oh + (((size_t)((m >> 11) * 16 + (k >> 6))) * 2048 \
                                      + (m & 2047)) * 64 + (k & 63);              \
            cp16(su(&Ah[buf][r * ST + cc * 8]), src);                             \
        }                                                                         \
        _Pragma("unroll")                                                         \
        for (int i = 0; i < 4; i++) {                                             \
            int id = tid + i * 256; int r = id >> 3, cc = id & 7;                 \
            cp16(su(&Bh[buf][r * ST + cc * 8]),                                   \
                 W + (size_t)(n0 + r) * 1024 + (k0) + cc * 8);                    \
        }                                                                         \
        cpcommit();                                                               \
    } while (0)

    OP_LOAD(0, 0);
    for (int it = 0; it < 16; it++) {
        if (it + 1 < 16) { OP_LOAD((it + 1) & 1, (it + 1) * 64); cpwait1(); }
        else cpwait0();
        __syncthreads();
        const __half* a_s = Ah[it & 1];
        const __half* b_s = Bh[it & 1];
#pragma unroll
        for (int ks = 0; ks < 4; ks++) {
            unsigned a[2][4];
#pragma unroll
            for (int ma = 0; ma < 2; ma++)
                ldsm4(a[ma], su(&a_s[(wm + ma * 16 + (lm & 1) * 8 + lr) * ST
                                     + ks * 16 + (lm >> 1) * 8]));
#pragma unroll
            for (int gb = 0; gb < 4; gb++) {
                unsigned r[4];
                ldsm4(r, su(&b_s[(wn + (gb * 2 + (lm >> 1)) * 8 + lr) * ST
                                 + ks * 16 + (lm & 1) * 8]));
                mma16(acc[0][gb * 2],     a[0], &r[0]);
                mma16(acc[1][gb * 2],     a[1], &r[0]);
                mma16(acc[0][gb * 2 + 1], a[0], &r[2]);
                mma16(acc[1][gb * 2 + 1], a[1], &r[2]);
            }
        }
        __syncthreads();
    }

#pragma unroll
    for (int ma = 0; ma < 2; ma++)
#pragma unroll
        for (int nb = 0; nb < 8; nb++) {
            int c0 = n0 + wn + nb * 8 + 2 * t;
            float b0 = __ldg(&bo[c0]), b1 = __ldg(&bo[c0 + 1]);
#pragma unroll
            for (int rr = 0; rr < 2; rr++) {
                int r = m0 + wm + ma * 16 + g + rr * 8;
                float2 v;
                v.x = acc[ma][nb][rr * 2 + 0] + b0;
                v.y = acc[ma][nb][rr * 2 + 1] + b1;
                *(float2*)&out[(size_t)r * 1024 + c0] = v;
            }
        }
}

// ============================================================
extern "C" void kernel_launch(void* const* d_in, const int* in_sizes, int n_in,
                              void* d_out, int out_size)
{
    const float* x  = (const float*)d_in[0];
    const float* wq = (const float*)d_in[1];
    const float* bq = (const float*)d_in[2];
    const float* wk = (const float*)d_in[3];
    const float* bk = (const float*)d_in[4];
    const float* wv = (const float*)d_in[5];
    const float* bv = (const float*)d_in[6];
    const float* wo = (const float*)d_in[7];
    const float* bo = (const float*)d_in[8];
    float* out = (float*)d_out;

    cudaFuncSetAttribute(proj_qkv_kernel,   cudaFuncAttributeMaxDynamicSharedMemorySize, GEMM_SMEM);
    cudaFuncSetAttribute(flash_attn_kernel, cudaFuncAttributeMaxDynamicSharedMemorySize, FLASH_SMEM);
    cudaFuncSetAttribute(outproj_kernel,    cudaFuncAttributeMaxDynamicSharedMemorySize, GEMM_SMEM);

    __half* Xh_p;  cudaGetSymbolAddress((void**)&Xh_p, Xh);
    __half* Wt_p;  cudaGetSymbolAddress((void**)&Wt_p, Wth);
    __half* Qp;    cudaGetSymbolAddress((void**)&Qp, Qh);
    __half* Kp;    cudaGetSymbolAddress((void**)&Kp, Kh);
    __half* Vp;    cudaGetSymbolAddress((void**)&Vp, Vh);

    static __half* h_tab[3];
    h_tab[0] = Qp; h_tab[1] = Kp; h_tab[2] = Vp;
    void* tab_dev; cudaGetSymbolAddress(&tab_dev, QKVout16);
    cudaMemcpyAsync(tab_dev, h_tab, sizeof(h_tab), cudaMemcpyHostToDevice);

    dim3 blk(256);
    const size_t WSZ = (size_t)D_MODEL * D_MODEL;

    {
        int n4 = (MROWS * D_MODEL) / 4;
        cvt_x_kernel<<<(n4 + 255) / 256, blk>>>(x, Xh_p, n4);
        cvt_wT_kernel<<<dim3(32, 32, 4), dim3(32, 8)>>>(wq, wk, wv, wo, Wt_p);
    }

    dim3 gqkv(D_MODEL / 128, MROWS / 128, 3);
    proj_qkv_kernel<<<gqkv, blk, GEMM_SMEM>>>(Xh_p, Wt_p, bq, bk, bv);

    flash_attn_kernel<<<dim3(SEQ / 128, BH), dim3(128), FLASH_SMEM>>>();

    outproj_kernel<<<dim3(D_MODEL / 128, MROWS / 128), blk, GEMM_SMEM>>>(
        Wt_p + 3 * WSZ, bo, out);
}

// round 17
// speedup vs baseline: 1.3323x; 1.0119x over previous
#include <cuda_runtime.h>
#include <cuda_fp16.h>

#define D_MODEL 1024
#define HEADS   16
#define DEPTH   64
#define BATCH   4
#define SEQ     2048
#define MROWS   (BATCH * SEQ)   /* 8192 */
#define BH      (BATCH * HEADS) /* 64   */

// ---- static scratch (allocation-free per harness rules) ----
__device__ __half Xh[(size_t)MROWS * D_MODEL];        // x in fp16
__device__ __half Wth[(size_t)4 * D_MODEL * D_MODEL]; // W^T fp16: [4][n][k]
__device__ __half Qh[(size_t)BH * SEQ * DEPTH];       // [bh][s][d], pre-scaled
__device__ __half Kh[(size_t)BH * SEQ * DEPTH];       // [bh][s][d]
__device__ __half Vh[(size_t)BH * DEPTH * SEQ];       // TRANSPOSED [bh][d][s]
__device__ __half Oh[(size_t)BH * SEQ * DEPTH];       // [bh][s][d]

__device__ __half* QKVout16[3];

#define SCL_F (0.125f * 1.4426950408889634f)   /* 1/sqrt(64) * log2(e) */

// ---------------- helpers ----------------
__device__ __forceinline__ unsigned su(const void* p) {
    return (unsigned)__cvta_generic_to_shared(p);
}
__device__ __forceinline__ void cp16(unsigned d, const void* s) {
    asm volatile("cp.async.cg.shared.global [%0], [%1], 16;" :: "r"(d), "l"(s));
}
__device__ __forceinline__ void cpcommit() { asm volatile("cp.async.commit_group;"); }
__device__ __forceinline__ void cpwait0() { asm volatile("cp.async.wait_group 0;"); }
__device__ __forceinline__ void cpwait1() { asm volatile("cp.async.wait_group 1;"); }

// pack two floats -> half2 (x = low element, y = high element)
__device__ __forceinline__ unsigned h2pack(float x, float y) {
    unsigned r;
    asm("cvt.rn.f16x2.f32 %0, %1, %2;" : "=r"(r) : "f"(y), "f"(x));
    return r;
}
__device__ __forceinline__ unsigned h2u(__half2 h) { return *(unsigned*)&h; }
__device__ __forceinline__ __half2 u2h(unsigned u) { return *(__half2*)&u; }

// fp16 mma m16n8k16, fp32 accumulate
__device__ __forceinline__ void mma16(float* c, const unsigned* a, const unsigned* b) {
    asm volatile(
        "mma.sync.aligned.m16n8k16.row.col.f32.f16.f16.f32 "
        "{%0,%1,%2,%3},{%4,%5,%6,%7},{%8,%9},{%0,%1,%2,%3};"
        : "+f"(c[0]), "+f"(c[1]), "+f"(c[2]), "+f"(c[3])
        : "r"(a[0]), "r"(a[1]), "r"(a[2]), "r"(a[3]), "r"(b[0]), "r"(b[1]));
}
// fp16 mma m16n8k16, fp16 accumulate (C/D packed half2 x2)
__device__ __forceinline__ void mma16h(unsigned* c, const unsigned* a, const unsigned* b) {
    asm volatile(
        "mma.sync.aligned.m16n8k16.row.col.f16.f16.f16.f16 "
        "{%0,%1},{%2,%3,%4,%5},{%6,%7},{%0,%1};"
        : "+r"(c[0]), "+r"(c[1])
        : "r"(a[0]), "r"(a[1]), "r"(a[2]), "r"(a[3]), "r"(b[0]), "r"(b[1]));
}
// ldmatrix x4 (non-transposed): lane 4r+c of each 8-lane group addresses row r
__device__ __forceinline__ void ldsm4(unsigned* r, unsigned addr) {
    asm volatile("ldmatrix.sync.aligned.m8n8.x4.shared.b16 {%0,%1,%2,%3}, [%4];"
        : "=r"(r[0]), "=r"(r[1]), "=r"(r[2]), "=r"(r[3]) : "r"(addr));
}

#define ST 72   /* smem row stride in halves = 144 bytes */

// ---------------- prep: x -> fp16 ----------------
__global__ __launch_bounds__(256) void cvt_x_kernel(
    const float* __restrict__ in, __half* __restrict__ out, int n4)
{
    int i = blockIdx.x * 256 + threadIdx.x;
    if (i < n4) {
        float4 v = ((const float4*)in)[i];
        uint2 o;
        o.x = h2pack(v.x, v.y);
        o.y = h2pack(v.z, v.w);
        ((uint2*)out)[i] = o;
    }
}

// ---------------- prep: transpose weights -> fp16  Wth[z][n][k] ----------------
__global__ __launch_bounds__(256) void cvt_wT_kernel(
    const float* __restrict__ w0, const float* __restrict__ w1,
    const float* __restrict__ w2, const float* __restrict__ w3,
    __half* __restrict__ out)
{
    __shared__ float t[32][33];
    const float* src = (blockIdx.z == 0) ? w0 : (blockIdx.z == 1) ? w1
                       : (blockIdx.z == 2) ? w2 : w3;
    __half* dst = out + (size_t)blockIdx.z * (size_t)D_MODEL * D_MODEL;
    int bx = blockIdx.x * 32;   // k tile
    int by = blockIdx.y * 32;   // n tile
#pragma unroll
    for (int j = 0; j < 4; j++)
        t[threadIdx.y + j * 8][threadIdx.x] =
            src[(size_t)(bx + threadIdx.y + j * 8) * D_MODEL + by + threadIdx.x];
    __syncthreads();
#pragma unroll
    for (int j = 0; j < 4; j++)
        dst[(size_t)(by + threadIdx.y + j * 8) * D_MODEL + bx + threadIdx.x] =
            __float2half_rn(t[threadIdx.x][threadIdx.y + j * 8]);
}

// ============================================================
// Kernel 1: MERGED QKV proj — 128 threads, tile 128x64, 3 CTAs/SM
//   4 warps x (32x64) warp tile; fused ldsm/mma; K chunks of 64.
// ============================================================
#define GEMM_SMEM ((128 + 64) * ST * 2 * 2)   /* 55296 bytes */

__global__ __launch_bounds__(128, 3) void proj_qkv_kernel(
    const __half* __restrict__ A, const __half* __restrict__ Wbase,
    const float* __restrict__ bq, const float* __restrict__ bk,
    const float* __restrict__ bv)
{
    extern __shared__ __half smh[];
    __half* Ah[2] = { smh, smh + 128 * ST };
    __half* Bh[2] = { smh + 2 * 128 * ST, smh + 2 * 128 * ST + 64 * ST };

    const int z = blockIdx.z;
    const __half* W = Wbase + (size_t)z * D_MODEL * D_MODEL;
    const float* bias = (z == 0) ? bq : (z == 1) ? bk : bv;
    __half* out = QKVout16[z];

    const int tid = threadIdx.x;
    const int m0 = blockIdx.y * 128, n0 = blockIdx.x * 64;
    const int warp = tid >> 5, lane = tid & 31;
    const int g = lane >> 2, t = lane & 3;
    const int lm = lane >> 3, lr = lane & 7;   // ldmatrix: matrix id, row
    const int wm = warp * 32;

    float acc[2][8][4] = {};

#define PROJ_LOAD(buf, k0)                                                        \
    do {                                                                          \
        _Pragma("unroll")                                                         \
        for (int i = 0; i < 8; i++) {                                             \
            int id = tid + i * 128; int r = id >> 3, cc = id & 7;                 \
            cp16(su(&Ah[buf][r * ST + cc * 8]),                                   \
                 A + (size_t)(m0 + r) * 1024 + (k0) + cc * 8);                    \
        }                                                                         \
        _Pragma("unroll")                                                         \
        for (int i = 0; i < 4; i++) {                                             \
            int id = tid + i * 128; int r = id >> 3, cc = id & 7;                 \
            cp16(su(&Bh[buf][r * ST + cc * 8]),                                   \
                 W + (size_t)(n0 + r) * 1024 + (k0) + cc * 8);                    \
        }                                                                         \
        cpcommit();                                                               \
    } while (0)

    PROJ_LOAD(0, 0);
    for (int it = 0; it < 16; it++) {
        if (it + 1 < 16) { PROJ_LOAD((it + 1) & 1, (it + 1) * 64); cpwait1(); }
        else cpwait0();
        __syncthreads();
        const __half* a_s = Ah[it & 1];
        const __half* b_s = Bh[it & 1];
#pragma unroll
        for (int ks = 0; ks < 4; ks++) {
            unsigned a[2][4];
#pragma unroll
            for (int ma = 0; ma < 2; ma++)
                ldsm4(a[ma], su(&a_s[(wm + ma * 16 + (lm & 1) * 8 + lr) * ST
                                     + ks * 16 + (lm >> 1) * 8]));
#pragma unroll
            for (int gb = 0; gb < 4; gb++) {
                unsigned r[4];
                ldsm4(r, su(&b_s[((gb * 2 + (lm >> 1)) * 8 + lr) * ST
                                 + ks * 16 + (lm & 1) * 8]));
                mma16(acc[0][gb * 2],     a[0], &r[0]);
                mma16(acc[1][gb * 2],     a[1], &r[0]);
                mma16(acc[0][gb * 2 + 1], a[0], &r[2]);
                mma16(acc[1][gb * 2 + 1], a[1], &r[2]);
            }
        }
        __syncthreads();
    }

    const float scale = (z == 0) ? SCL_F : 1.0f;
#pragma unroll
    for (int ma = 0; ma < 2; ma++)
#pragma unroll
        for (int nb = 0; nb < 8; nb++) {
            int c0 = n0 + nb * 8 + 2 * t;
            float b0 = __ldg(&bias[c0]), b1 = __ldg(&bias[c0 + 1]);
            int h = c0 >> 6, d = c0 & 63;
#pragma unroll
            for (int rr = 0; rr < 2; rr++) {
                int r = m0 + wm + ma * 16 + g + rr * 8;
                int bb = r >> 11, ss = r & 2047;
                float vx = (acc[ma][nb][rr * 2 + 0] + b0) * scale;
                float vy = (acc[ma][nb][rr * 2 + 1] + b1) * scale;
                if (z != 2) {
                    *(unsigned*)&out[(((size_t)(bb * 16 + h)) * 2048 + ss) * 64 + d] =
                        h2pack(vx, vy);
                } else {
                    __half* vb = out + (size_t)(bb * 16 + h) * 64 * 2048;
                    vb[(size_t)d * 2048 + ss]       = __float2half_rn(vx);
                    vb[(size_t)(d + 1) * 2048 + ss] = __float2half_rn(vy);
                }
            }
        }
}

// ============================================================
// Kernel 2: FLASH ATTENTION — unchanged from R16 (validated)
// ============================================================
#define FLASH_SMEM ((128 * ST + 4 * 64 * ST) * 2)   /* 55296 bytes */
#define ONES2 0x3C003C00u                            /* half2(1,1) */

__global__ __launch_bounds__(128, 3) void flash_attn_kernel()
{
    extern __shared__ __half smh[];
    __half* Qs = smh;                                    // 128 x ST
    __half* Ks[2] = { smh + 128 * ST, smh + 128 * ST + 64 * ST };
    __half* Vs[2] = { smh + 128 * ST + 2 * 64 * ST, smh + 128 * ST + 3 * 64 * ST };

    const int bh = blockIdx.y;
    const int m0 = blockIdx.x * 128;
    const __half* Qp = Qh + (size_t)bh * SEQ * DEPTH;
    const __half* Kp = Kh + (size_t)bh * SEQ * DEPTH;
    const __half* Vp = Vh + (size_t)bh * DEPTH * SEQ;   // [d][s]
    __half* Op = Oh + (size_t)bh * SEQ * DEPTH;

    const int tid = threadIdx.x;
    const int warp = tid >> 5, lane = tid & 31;
    const int g = lane >> 2, t = lane & 3;
    const int lm = lane >> 3, lr = lane & 7;
    const int wq0 = warp * 32;
    const unsigned FULL = 0xffffffffu;

#pragma unroll
    for (int i = 0; i < 8; i++) {
        int id = tid + i * 128; int r = id >> 3, c = id & 7;
        cp16(su(&Qs[r * ST + c * 8]), Qp + (size_t)(m0 + r) * 64 + c * 8);
    }
    cpcommit();

#define KV_LOAD(buf, kv0)                                                         \
    do {                                                                          \
        _Pragma("unroll")                                                         \
        for (int i = 0; i < 4; i++) {                                             \
            int id = tid + i * 128; int r = id >> 3, c = id & 7;                  \
            cp16(su(&Ks[buf][r * ST + c * 8]),                                    \
                 Kp + (size_t)((kv0) + r) * 64 + c * 8);                          \
        }                                                                         \
        _Pragma("unroll")                                                         \
        for (int i = 0; i < 4; i++) {                                             \
            int id = tid + i * 128; int r = id >> 3, c = id & 7;                  \
            cp16(su(&Vs[buf][r * ST + c * 8]),                                    \
                 Vp + (size_t)r * 2048 + (kv0) + c * 8);                          \
        }                                                                         \
        cpcommit();                                                               \
    } while (0)

    KV_LOAD(0, 0);
    cpwait1();
    __syncthreads();

    // running max per ma: half2(lo = row g, hi = row g+8)
    __half2 mr2[2];
    mr2[0] = __float2half2_rn(-60000.f);
    mr2[1] = __float2half2_rn(-60000.f);

    // o[ma][0..7] = output cols; o[ma][8] = row-sum column (l), fp32 acc
    float o[2][9][4] = {};

    for (int j = 0; j < 32; j++) {
        if (j + 1 < 32) { KV_LOAD((j + 1) & 1, (j + 1) * 64); cpwait1(); }
        else cpwait0();
        __syncthreads();
        const __half* ks = Ks[j & 1];
        const __half* vs = Vs[j & 1];

        // ---- S = Q K^T : fp16 accumulate; fused ldsm/mma ----
        unsigned acc2[2][8][2];
#pragma unroll
        for (int ma = 0; ma < 2; ma++)
#pragma unroll
            for (int nb = 0; nb < 8; nb++) {
                acc2[ma][nb][0] = 0u; acc2[ma][nb][1] = 0u;
            }

#pragma unroll
        for (int kb = 0; kb < 4; kb++) {
            unsigned a[2][4];
#pragma unroll
            for (int ma = 0; ma < 2; ma++)
                ldsm4(a[ma], su(&Qs[(wq0 + ma * 16 + (lm & 1) * 8 + lr) * ST
                                    + kb * 16 + (lm >> 1) * 8]));
#pragma unroll
            for (int gb = 0; gb < 4; gb++) {
                unsigned r[4];
                ldsm4(r, su(&ks[((gb * 2 + (lm >> 1)) * 8 + lr) * ST
                                + kb * 16 + (lm & 1) * 8]));
                mma16h(acc2[0][gb * 2],     a[0], &r[0]);
                mma16h(acc2[1][gb * 2],     a[1], &r[0]);
                mma16h(acc2[0][gb * 2 + 1], a[0], &r[2]);
                mma16h(acc2[1][gb * 2 + 1], a[1], &r[2]);
            }
        }

        // ---- max reduction in half2 domain ----
        float al[4];
#pragma unroll
        for (int ma = 0; ma < 2; ma++) {
            __half2 x0 = u2h(acc2[ma][0][0]), x1 = u2h(acc2[ma][0][1]);
#pragma unroll
            for (int nb = 1; nb < 8; nb++) {
                x0 = __hmax2(x0, u2h(acc2[ma][nb][0]));
                x1 = __hmax2(x1, u2h(acc2[ma][nb][1]));
            }
            __half2 mm = __halves2half2(
                __hmax(__low2half(x0), __high2half(x0)),
                __hmax(__low2half(x1), __high2half(x1)));
            mm = __hmax2(mm, u2h(__shfl_xor_sync(FULL, h2u(mm), 1)));
            mm = __hmax2(mm, u2h(__shfl_xor_sync(FULL, h2u(mm), 2)));
            __half2 nm = __hmax2(mr2[ma], mm);
            __half2 a2 = h2exp2(__hsub2(mr2[ma], nm));
            mr2[ma] = nm;
            al[ma * 2 + 0] = __low2float(a2);
            al[ma * 2 + 1] = __high2float(a2);
        }

        // ---- rescale O (incl. the l column) ----
#pragma unroll
        for (int ma = 0; ma < 2; ma++)
#pragma unroll
            for (int nb = 0; nb < 9; nb++) {
                o[ma][nb][0] *= al[ma * 2 + 0]; o[ma][nb][1] *= al[ma * 2 + 0];
                o[ma][nb][2] *= al[ma * 2 + 1]; o[ma][nb][3] *= al[ma * 2 + 1];
            }

        // ---- O += P @ V, P = exp2(acc2 - m); fused ldsm/mma ----
#pragma unroll
        for (int kb = 0; kb < 4; kb++) {
            unsigned ap[2][4];
#pragma unroll
            for (int ma = 0; ma < 2; ma++) {
                __half2 m0b = __low2half2(mr2[ma]);
                __half2 m1b = __high2half2(mr2[ma]);
                ap[ma][0] = h2u(h2exp2(__hsub2(u2h(acc2[ma][2 * kb][0]),     m0b)));
                ap[ma][1] = h2u(h2exp2(__hsub2(u2h(acc2[ma][2 * kb][1]),     m1b)));
                ap[ma][2] = h2u(h2exp2(__hsub2(u2h(acc2[ma][2 * kb + 1][0]), m0b)));
                ap[ma][3] = h2u(h2exp2(__hsub2(u2h(acc2[ma][2 * kb + 1][1]), m1b)));
            }
#pragma unroll
            for (int gb = 0; gb < 4; gb++) {
                unsigned r[4];
                ldsm4(r, su(&vs[((gb * 2 + (lm >> 1)) * 8 + lr) * ST
                                + kb * 16 + (lm & 1) * 8]));
                mma16(o[0][gb * 2],     ap[0], &r[0]);
                mma16(o[1][gb * 2],     ap[1], &r[0]);
                mma16(o[0][gb * 2 + 1], ap[0], &r[2]);
                mma16(o[1][gb * 2 + 1], ap[1], &r[2]);
            }
            // ones column (row-sum l)
            {
                unsigned onesb[2] = { ONES2, ONES2 };
                mma16(o[0][8], ap[0], onesb);
                mma16(o[1][8], ap[1], onesb);
            }
        }
        __syncthreads();
    }

    // ---- epilogue: O /= l (from ones column), fp16 store ----
#pragma unroll
    for (int ma = 0; ma < 2; ma++) {
        float inv0 = 1.f / o[ma][8][0];
        float inv1 = 1.f / o[ma][8][2];
#pragma unroll
        for (int nb = 0; nb < 8; nb++) {
            int c0 = nb * 8 + 2 * t;
            {
                int r = m0 + wq0 + ma * 16 + g;
                *(unsigned*)&Op[(size_t)r * 64 + c0] =
                    h2pack(o[ma][nb][0] * inv0, o[ma][nb][1] * inv0);
            }
            {
                int r = m0 + wq0 + ma * 16 + g + 8;
                *(unsigned*)&Op[(size_t)r * 64 + c0] =
                    h2pack(o[ma][nb][2] * inv1, o[ma][nb][3] * inv1);
            }
        }
    }
}

// ============================================================
// Kernel 3: outproj — 128 threads, tile 128x64, 3 CTAs/SM
// ============================================================
__global__ __launch_bounds__(128, 3) void outproj_kernel(
    const __half* __restrict__ W, const float* __restrict__ bo,
    float* __restrict__ out)
{
    extern __shared__ __half smh[];
    __half* Ah[2] = { smh, smh + 128 * ST };
    __half* Bh[2] = { smh + 2 * 128 * ST, smh + 2 * 128 * ST + 64 * ST };

    const int tid = threadIdx.x;
    const int m0 = blockIdx.y * 128, n0 = blockIdx.x * 64;
    const int warp = tid >> 5, lane = tid & 31;
    const int g = lane >> 2, t = lane & 3;
    const int lm = lane >> 3, lr = lane & 7;
    const int wm = warp * 32;

    float acc[2][8][4] = {};

#define OP_LOAD(buf, k0)                                                          \
    do {                                                                          \
        _Pragma("unroll")                                                         \
        for (int i = 0; i < 8; i++) {                                             \
            int id = tid + i * 128; int r = id >> 3, cc = id & 7;                 \
            int m = m0 + r; int k = (k0) + cc * 8;                                \
            const __half* src = Oh + (((size_t)((m >> 11) * 16 + (k >> 6))) * 2048 \
                                      + (m & 2047)) * 64 + (k & 63);              \
            cp16(su(&Ah[buf][r * ST + cc * 8]), src);                             \
        }                                                                         \
        _Pragma("unroll")                                                         \
        for (int i = 0; i < 4; i++) {                                             \
            int id = tid + i * 128; int r = id >> 3, cc = id & 7;                 \
            cp16(su(&Bh[buf][r * ST + cc * 8]),                                   \
                 W + (size_t)(n0 + r) * 1024 + (k0) + cc * 8);                    \
        }                                                                         \
        cpcommit();                                                               \
    } while (0)

    OP_LOAD(0, 0);
    for (int it = 0; it < 16; it++) {
        if (it + 1 < 16) { OP_LOAD((it + 1) & 1, (it + 1) * 64); cpwait1(); }
        else cpwait0();
        __syncthreads();
        const __half* a_s = Ah[it & 1];
        const __half* b_s = Bh[it & 1];
#pragma unroll
        for (int ks = 0; ks < 4; ks++) {
            unsigned a[2][4];
#pragma unroll
            for (int ma = 0; ma < 2; ma++)
                ldsm4(a[ma], su(&a_s[(wm + ma * 16 + (lm & 1) * 8 + lr) * ST
                                     + ks * 16 + (lm >> 1) * 8]));
#pragma unroll
            for (int gb = 0; gb < 4; gb++) {
                unsigned r[4];
                ldsm4(r, su(&b_s[((gb * 2 + (lm >> 1)) * 8 + lr) * ST
                                 + ks * 16 + (lm & 1) * 8]));
                mma16(acc[0][gb * 2],     a[0], &r[0]);
                mma16(acc[1][gb * 2],     a[1], &r[0]);
                mma16(acc[0][gb * 2 + 1], a[0], &r[2]);
                mma16(acc[1][gb * 2 + 1], a[1], &r[2]);
            }
        }
        __syncthreads();
    }

#pragma unroll
    for (int ma = 0; ma < 2; ma++)
#pragma unroll
        for (int nb = 0; nb < 8; nb++) {
            int c0 = n0 + nb * 8 + 2 * t;
            float b0 = __ldg(&bo[c0]), b1 = __ldg(&bo[c0 + 1]);
#pragma unroll
            for (int rr = 0; rr < 2; rr++) {
                int r = m0 + wm + ma * 16 + g + rr * 8;
                float2 v;
                v.x = acc[ma][nb][rr * 2 + 0] + b0;
                v.y = acc[ma][nb][rr * 2 + 1] + b1;
                *(float2*)&out[(size_t)r * 1024 + c0] = v;
            }
        }
}

// ============================================================
extern "C" void kernel_launch(void* const* d_in, const int* in_sizes, int n_in,
                              void* d_out, int out_size)
{
    const float* x  = (const float*)d_in[0];
    const float* wq = (const float*)d_in[1];
    const float* bq = (const float*)d_in[2];
    const float* wk = (const float*)d_in[3];
    const float* bk = (const float*)d_in[4];
    const float* wv = (const float*)d_in[5];
    const float* bv = (const float*)d_in[6];
    const float* wo = (const float*)d_in[7];
    const float* bo = (const float*)d_in[8];
    float* out = (float*)d_out;

    cudaFuncSetAttribute(proj_qkv_kernel,   cudaFuncAttributeMaxDynamicSharedMemorySize, GEMM_SMEM);
    cudaFuncSetAttribute(flash_attn_kernel, cudaFuncAttributeMaxDynamicSharedMemorySize, FLASH_SMEM);
    cudaFuncSetAttribute(outproj_kernel,    cudaFuncAttributeMaxDynamicSharedMemorySize, GEMM_SMEM);

    __half* Xh_p;  cudaGetSymbolAddress((void**)&Xh_p, Xh);
    __half* Wt_p;  cudaGetSymbolAddress((void**)&Wt_p, Wth);
    __half* Qp;    cudaGetSymbolAddress((void**)&Qp, Qh);
    __half* Kp;    cudaGetSymbolAddress((void**)&Kp, Kh);
    __half* Vp;    cudaGetSymbolAddress((void**)&Vp, Vh);

    static __half* h_tab[3];
    h_tab[0] = Qp; h_tab[1] = Kp; h_tab[2] = Vp;
    void* tab_dev; cudaGetSymbolAddress(&tab_dev, QKVout16);
    cudaMemcpyAsync(tab_dev, h_tab, sizeof(h_tab), cudaMemcpyHostToDevice);

    dim3 blk(256);
    const size_t WSZ = (size_t)D_MODEL * D_MODEL;

    {
        int n4 = (MROWS * D_MODEL) / 4;
        cvt_x_kernel<<<(n4 + 255) / 256, blk>>>(x, Xh_p, n4);
        cvt_wT_kernel<<<dim3(32, 32, 4), dim3(32, 8)>>>(wq, wk, wv, wo, Wt_p);
    }

    // merged QKV: tile 128x64 -> grid (16, 64, 3)
    dim3 gqkv(D_MODEL / 64, MROWS / 128, 3);
    proj_qkv_kernel<<<gqkv, dim3(128), GEMM_SMEM>>>(Xh_p, Wt_p, bq, bk, bv);

    flash_attn_kernel<<<dim3(SEQ / 128, BH), dim3(128), FLASH_SMEM>>>();

    outproj_kernel<<<dim3(D_MODEL / 64, MROWS / 128), dim3(128), GEMM_SMEM>>>(
        Wt_p + 3 * WSZ, bo, out);
}